// round 4
// baseline (speedup 1.0000x reference)
#include <cuda_runtime.h>
#include <math.h>
#include <stdint.h>

#define HW    16384
#define Bn    8
#define HIDn  170
#define XSTR  68
#define WSTR  68
#define COSTR 769

// ---------------- scratch (static device memory) ----------------
__device__ float g_bufR[Bn * 64 * HW];
__device__ float g_bufX[Bn * 64 * HW];
__device__ float g_bufG[Bn * 64 * HW];
__device__ float g_big2[Bn * 340 * HW];
__device__ float g_attn[Bn * 8 * 64];
__device__ float g_part[64 * 8 * 80];
__device__ float g_M[Bn * 64 * 64];

__device__ __forceinline__ float gelu_f(float x) {
    return 0.5f * x * (1.0f + erff(x * 0.70710678118654752f));
}
__device__ __forceinline__ uint32_t f2tf32(float x) {
    uint32_t r; asm("cvt.rna.tf32.f32 %0, %1;" : "=r"(r) : "f"(x)); return r;
}
__device__ __forceinline__ void ldsm4(uint32_t* a, uint32_t addr) {
    asm volatile("ldmatrix.sync.aligned.m8n8.x4.shared.b16 {%0,%1,%2,%3}, [%4];"
        : "=r"(a[0]), "=r"(a[1]), "=r"(a[2]), "=r"(a[3]) : "r"(addr));
}
__device__ __forceinline__ void mma_tf32(float* d, const uint32_t* a, uint32_t b0, uint32_t b1) {
    asm volatile("mma.sync.aligned.m16n8k8.row.col.f32.tf32.tf32.f32 "
        "{%0,%1,%2,%3}, {%4,%5,%6,%7}, {%8,%9}, {%0,%1,%2,%3};"
        : "+f"(d[0]), "+f"(d[1]), "+f"(d[2]), "+f"(d[3])
        : "r"(a[0]), "r"(a[1]), "r"(a[2]), "r"(a[3]), "r"(b0), "r"(b1));
}

// =================================================================
// FUSED: LN (algebraic) + conv1x1 (Cin=64, tf32 TC) + dwconv3x3.
// Block: 32 out-ch x 4 output rows (512 px), computes 6 conv rows
// (halo recompute) into smem, stencils, writes only dwconv output.
// grid: (ceil(Cout/32), 32 rowgroups, Bn)
// =================================================================
__global__ void __launch_bounds__(256, 1)
convdw_kernel(const float* __restrict__ in, const float* __restrict__ addp,
              const float* __restrict__ lnw, const float* __restrict__ lnb,
              const float* __restrict__ wt, const float* __restrict__ dww,
              float* __restrict__ out, int Cout, int shift)
{
    extern __shared__ float sm[];
    float* Xh   = sm;                    // [256][68]
    float* BF   = sm + 256 * XSTR;       // [8kb][4n8][32][4]
    float* CO   = BF + 4096;             // [32][COSTR] conv out, 6 rows (768 cols)
    float* mu_s = CO + 32 * COSTR;       // [256]
    float* rs_s = mu_s + 256;            // [256]
    float* sg_s = rs_s + 256;            // [32]
    float* sb_s = sg_s + 32;             // [32]
    float* dws  = sb_s + 32;             // [288]

    int ogbase = blockIdx.x * 32;
    int r0 = blockIdx.y * 4;
    int b  = blockIdx.z;
    int tid = threadIdx.x;
    int warp = tid >> 5, lane = tid & 31;
    const float* inb = in + (size_t)b * 64 * HW;
    const float* adb = addp ? addp + (size_t)b * 64 * HW : nullptr;

    // ---- stage W fragments (hi/lo tf32 split, gamma folded) ----
    #pragma unroll
    for (int i = 0; i < 8; i++) {
        int e = i * 256 + tid;
        int o = e >> 6, k = e & 63;
        int og = ogbase + o;
        float wv = (og < Cout) ? wt[(size_t)og * 64 + k] * lnw[k] : 0.f;
        uint32_t whb = f2tf32(wv);
        float wlo = wv - __uint_as_float(whb);
        uint32_t wlb = f2tf32(wlo);
        int kb = k >> 3, kw = k & 7, n8 = o >> 3, nn = o & 7;
        int bl = nn * 4 + (kw & 3);
        int slot = kw >> 2;
        float* dst = &BF[((kb * 4 + n8) * 32 + bl) * 4];
        dst[slot]     = __uint_as_float(whb);
        dst[slot + 2] = __uint_as_float(wlb);
    }
    if (tid < 32) {
        float sg = 0.f, sb = 0.f;
        if (ogbase + tid < Cout) {
            const float* wr = wt + (size_t)(ogbase + tid) * 64;
            #pragma unroll 8
            for (int k = 0; k < 64; k++) { sg += wr[k] * lnw[k]; sb += wr[k] * lnb[k]; }
        }
        sg_s[tid] = sg; sb_s[tid] = sb;
    }
    for (int e = tid; e < 288; e += 256) {
        int ch = e / 9, k = e - ch * 9;
        dws[e] = (ogbase + ch < Cout) ? dww[(size_t)(ogbase + ch) * 9 + k] : 0.f;
    }

    // ---- 3 subtiles of 2 rows covering conv rows r0-1 .. r0+4 ----
    for (int s = 0; s < 3; s++) {
        __syncthreads();
        int ps = (r0 - 1 + 2 * s) * 128;
        int p = ps + tid;
        bool vrow = (p >= 0) && (p < HW);
        // stage X + LN stats (this thread's pixel row in Xh)
        float s_sum = 0.f, s_sq = 0.f;
        if (vrow) {
            int ip = p;
            if (shift) {
                int hh = ((p >> 7) + shift) & 127, ww = ((p & 127) + shift) & 127;
                ip = (hh << 7) | ww;
            }
            #pragma unroll 4
            for (int j4 = 0; j4 < 16; j4++) {
                float v4[4];
                #pragma unroll
                for (int jj = 0; jj < 4; jj++) {
                    int c = j4 * 4 + jj;
                    float v = inb[(size_t)c * HW + ip];
                    if (adb) v += adb[(size_t)c * HW + ip];
                    s_sum += v; s_sq += v * v;
                    v4[jj] = __uint_as_float(f2tf32(v));
                }
                *(float4*)&Xh[tid * XSTR + j4 * 4] = make_float4(v4[0], v4[1], v4[2], v4[3]);
            }
        } else {
            #pragma unroll
            for (int j4 = 0; j4 < 16; j4++)
                *(float4*)&Xh[tid * XSTR + j4 * 4] = make_float4(0.f, 0.f, 0.f, 0.f);
        }
        float m = s_sum * 0.015625f;
        float var = s_sq * 0.015625f - m * m;
        mu_s[tid] = m;
        rs_s[tid] = rsqrtf(fmaxf(var, 0.f) + 1e-5f);
        __syncthreads();

        // GEMM: 8 warps x 32px, 32 out
        float accD[2][4][4];
        #pragma unroll
        for (int t = 0; t < 2; t++)
            #pragma unroll
            for (int n = 0; n < 4; n++)
                #pragma unroll
                for (int q = 0; q < 4; q++) accD[t][n][q] = 0.f;
        uint32_t xbase = (uint32_t)__cvta_generic_to_shared(Xh);
        int r = lane & 7, madd8 = (lane >> 3) & 1, gsel = lane >> 4;
        uint32_t a_off0 = xbase + (((warp * 32) + r + madd8 * 8) * XSTR + gsel * 4) * 4;
        #pragma unroll
        for (int kb = 0; kb < 8; kb++) {
            uint32_t A0[4], A1[4];
            uint32_t addr0 = a_off0 + kb * 32;
            ldsm4(A0, addr0);
            ldsm4(A1, addr0 + 16 * XSTR * 4);
            const float4* bfk = (const float4*)&BF[(kb * 4) * 32 * 4];
            #pragma unroll
            for (int n8 = 0; n8 < 4; n8++) {
                float4 bv = bfk[n8 * 32 + lane];
                uint32_t bh0 = __float_as_uint(bv.x), bh1 = __float_as_uint(bv.y);
                uint32_t bl0 = __float_as_uint(bv.z), bl1 = __float_as_uint(bv.w);
                mma_tf32(accD[0][n8], A0, bh0, bh1);
                mma_tf32(accD[0][n8], A0, bl0, bl1);
                mma_tf32(accD[1][n8], A1, bh0, bh1);
                mma_tf32(accD[1][n8], A1, bl0, bl1);
            }
        }
        // epilogue: LN transform -> CO
        int gq = lane >> 2, oq = (lane & 3) * 2;
        int cbase = s * 256;
        #pragma unroll
        for (int t = 0; t < 2; t++) {
            int pxa = warp * 32 + t * 16 + gq;
            int pxb = pxa + 8;
            float mua = mu_s[pxa], rsa_ = rs_s[pxa];
            float mub = mu_s[pxb], rsb = rs_s[pxb];
            #pragma unroll
            for (int n8 = 0; n8 < 4; n8++) {
                #pragma unroll
                for (int q = 0; q < 2; q++) {
                    int ol = n8 * 8 + oq + q;
                    float sg = sg_s[ol], sb = sb_s[ol];
                    CO[ol * COSTR + cbase + pxa] = rsa_ * (accD[t][n8][q]     - mua * sg) + sb;
                    CO[ol * COSTR + cbase + pxb] = rsb  * (accD[t][n8][q + 2] - mub * sg) + sb;
                }
            }
        }
    }
    __syncthreads();

    // ---- dwconv 3x3 over CO, write 32ch x 4 rows ----
    #pragma unroll
    for (int i = 0; i < 8; i++) {
        int seg = i * 256 + tid;
        int ch = seg >> 6;
        int rem = seg & 63;
        int orow = rem >> 4;
        int x0 = (rem & 15) << 3;
        int og = ogbase + ch;
        if (og < Cout) {
            const float* wc = dws + ch * 9;
            float acc[8] = {0.f,0.f,0.f,0.f,0.f,0.f,0.f,0.f};
            #pragma unroll
            for (int dy = 0; dy < 3; dy++) {
                int grow = r0 + orow + dy - 1;
                if ((unsigned)grow > 127u) continue;
                const float* crow = CO + ch * COSTR + (orow + dy) * 128;
                float mbuf[10];
                mbuf[0] = (x0 > 0)   ? crow[x0 - 1] : 0.f;
                #pragma unroll
                for (int j = 0; j < 8; j++) mbuf[j + 1] = crow[x0 + j];
                mbuf[9] = (x0 < 120) ? crow[x0 + 8] : 0.f;
                float wa = wc[dy * 3], wb = wc[dy * 3 + 1], wcc = wc[dy * 3 + 2];
                #pragma unroll
                for (int j = 0; j < 8; j++)
                    acc[j] += wa * mbuf[j] + wb * mbuf[j + 1] + wcc * mbuf[j + 2];
            }
            float* op = out + ((size_t)b * Cout + og) * HW + (r0 + orow) * 128 + x0;
            *(float4*)op       = make_float4(acc[0], acc[1], acc[2], acc[3]);
            *(float4*)(op + 4) = make_float4(acc[4], acc[5], acc[6], acc[7]);
        }
    }
}

// =================================================================
// gated+resid tensor-core conv (Cin=170 phys 340) — unchanged scheme
// =================================================================
__global__ void __launch_bounds__(256, 2)
convtc_kernel(const float* __restrict__ in, const float* __restrict__ wt,
              float* __restrict__ out, const float* __restrict__ resid)
{
    extern __shared__ float sm[];
    float* Xh = sm;                 // [256][68]
    float* BF = sm + 256 * XSTR;    // [8][8][32][4]

    const int Cin = 170, inCh = 340, Cout = 64;
    int b = blockIdx.z, p0 = blockIdx.x * 256;
    int tid = threadIdx.x;
    int warp = tid >> 5, lane = tid & 31;
    int ip = p0 + tid;
    const float* inb = in + (size_t)b * inCh * HW;

    float accD[2][8][4];
    #pragma unroll
    for (int t = 0; t < 2; t++)
        #pragma unroll
        for (int n = 0; n < 8; n++)
            #pragma unroll
            for (int q = 0; q < 4; q++) accD[t][n][q] = 0.f;

    for (int ch = 0; ch < 3; ch++) {
        if (ch) __syncthreads();
        int c0 = ch << 6;
        #pragma unroll 4
        for (int j4 = 0; j4 < 16; j4++) {
            float v4[4];
            #pragma unroll
            for (int jj = 0; jj < 4; jj++) {
                int c = c0 + j4 * 4 + jj;
                float v = 0.f;
                if (c < Cin) {
                    float a = inb[(size_t)c * HW + ip];
                    float g = inb[(size_t)(c + HIDn) * HW + ip];
                    v = gelu_f(a) * g;
                }
                v4[jj] = __uint_as_float(f2tf32(v));
            }
            *(float4*)&Xh[tid * XSTR + j4 * 4] = make_float4(v4[0], v4[1], v4[2], v4[3]);
        }
        #pragma unroll
        for (int i = 0; i < 16; i++) {
            int e = i * 256 + tid;
            int o = e >> 6, k = e & 63;
            int kg = c0 + k;
            float wv = (kg < Cin) ? wt[(size_t)o * Cin + kg] : 0.f;
            uint32_t whb = f2tf32(wv);
            float wlo = wv - __uint_as_float(whb);
            uint32_t wlb = f2tf32(wlo);
            int kb = k >> 3, kw = k & 7, n8 = o >> 3, nn = o & 7;
            int bl = nn * 4 + (kw & 3);
            int slot = kw >> 2;
            float* dst = &BF[((kb * 8 + n8) * 32 + bl) * 4];
            dst[slot]     = __uint_as_float(whb);
            dst[slot + 2] = __uint_as_float(wlb);
        }
        __syncthreads();
        uint32_t xbase = (uint32_t)__cvta_generic_to_shared(Xh);
        int r = lane & 7, madd8 = (lane >> 3) & 1, gsel = lane >> 4;
        uint32_t a_off0 = xbase + (((warp * 32) + r + madd8 * 8) * XSTR + gsel * 4) * 4;
        #pragma unroll
        for (int kb = 0; kb < 8; kb++) {
            uint32_t A0[4], A1[4];
            uint32_t addr0 = a_off0 + kb * 32;
            ldsm4(A0, addr0);
            ldsm4(A1, addr0 + 16 * XSTR * 4);
            const float4* bfk = (const float4*)&BF[(kb * 8) * 32 * 4];
            #pragma unroll
            for (int n8 = 0; n8 < 8; n8++) {
                float4 bv = bfk[n8 * 32 + lane];
                uint32_t bh0 = __float_as_uint(bv.x), bh1 = __float_as_uint(bv.y);
                uint32_t bl0 = __float_as_uint(bv.z), bl1 = __float_as_uint(bv.w);
                mma_tf32(accD[0][n8], A0, bh0, bh1);
                mma_tf32(accD[0][n8], A0, bl0, bl1);
                mma_tf32(accD[1][n8], A1, bh0, bh1);
                mma_tf32(accD[1][n8], A1, bl0, bl1);
            }
        }
    }
    int gq = lane >> 2, oq = (lane & 3) * 2;
    #pragma unroll
    for (int t = 0; t < 2; t++) {
        int pxa = warp * 32 + t * 16 + gq;
        int pxb = pxa + 8;
        #pragma unroll
        for (int n8 = 0; n8 < 8; n8++) {
            #pragma unroll
            for (int q = 0; q < 2; q++) {
                int og = n8 * 8 + oq + q;
                float v0 = accD[t][n8][q]     + resid[((size_t)b * 64 + og) * HW + p0 + pxa];
                float v1 = accD[t][n8][q + 2] + resid[((size_t)b * 64 + og) * HW + p0 + pxb];
                size_t obase = ((size_t)b * 64 + og) * HW + p0;
                out[obase + pxa] = v0;
                out[obase + pxb] = v1;
            }
        }
    }
}

// =================================================================
// RSA window attention + fused proj conv + inverse roll
// =================================================================
__global__ void __launch_bounds__(256, 3)
rsa_attn_kernel(const float* __restrict__ qkv, const float* __restrict__ pw,
                float* __restrict__ out, const float* __restrict__ temp)
{
    extern __shared__ float sm[];
    float* A   = sm;                     // q[p][c] -> v[c][p]
    float* B   = sm + 64 * WSTR;         // k[p][c] -> out[d][p]
    float* C   = sm + 2 * 64 * WSTR;     // attn[c][d] -> proj out [o][p]
    float* Pw  = sm + 3 * 64 * WSTR;     // proj w [d][o]
    float* inv = Pw + 64 * WSTR;
    int blk = blockIdx.x;
    int b = blk >> 8, win = blk & 255;
    int wy = win >> 4, wx = win & 15;
    int tid = threadIdx.x;
    size_t qbase = (size_t)b * 192 * HW;

    for (int e = tid; e < 4096; e += 256) {
        int p = e & 63, c = e >> 6;
        int gp = (((wy << 3) + (p >> 3)) << 7) | ((wx << 3) + (p & 7));
        A[p * WSTR + c] = qkv[qbase + c * HW + gp];
        B[p * WSTR + c] = qkv[qbase + (64 + c) * HW + gp];
        Pw[(e & 63) * WSTR + (e >> 6)] = pw[e];   // Pw[d][o] = pw[o*64+d] -> e: o=e>>6,d=e&63
    }
    __syncthreads();
    if (tid < 64) {
        int p = tid;
        float nq = 0.f, nk = 0.f;
        #pragma unroll
        for (int c = 0; c < 64; c++) {
            float a = A[p * WSTR + c]; nq += a * a;
            float bb = B[p * WSTR + c]; nk += bb * bb;
        }
        inv[p] = 1.0f / (fmaxf(sqrtf(nq), 1e-12f) * fmaxf(sqrtf(nk), 1e-12f));
    }
    __syncthreads();
    for (int e4 = tid; e4 < 1024; e4 += 256) {
        int p = e4 >> 4, c4 = e4 & 15;
        float iv = inv[p];
        float4 v = ((float4*)B)[p * (WSTR / 4) + c4];
        v.x *= iv; v.y *= iv; v.z *= iv; v.w *= iv;
        ((float4*)B)[p * (WSTR / 4) + c4] = v;
    }
    __syncthreads();
    float tscale = temp[0];
    {   // GEMM1: attn
        int c0 = (tid >> 4) << 2, d0 = (tid & 15) << 2;
        float s[4][4] = {};
        #pragma unroll 4
        for (int p = 0; p < 64; p++) {
            float4 qv = *(const float4*)(A + p * WSTR + c0);
            float4 kv = *(const float4*)(B + p * WSTR + d0);
            float qr[4] = {qv.x, qv.y, qv.z, qv.w};
            float kr[4] = {kv.x, kv.y, kv.z, kv.w};
            #pragma unroll
            for (int i = 0; i < 4; i++)
                #pragma unroll
                for (int j = 0; j < 4; j++) s[i][j] += qr[i] * kr[j];
        }
        #pragma unroll
        for (int i = 0; i < 4; i++)
            *(float4*)(C + (c0 + i) * WSTR + d0) =
                make_float4(fmaxf(0.f, tscale * s[i][0]), fmaxf(0.f, tscale * s[i][1]),
                            fmaxf(0.f, tscale * s[i][2]), fmaxf(0.f, tscale * s[i][3]));
    }
    __syncthreads();
    for (int e = tid; e < 4096; e += 256) {   // v -> A [c][p]
        int p = e & 63, c = e >> 6;
        int gp = (((wy << 3) + (p >> 3)) << 7) | ((wx << 3) + (p & 7));
        A[c * WSTR + p] = qkv[qbase + (128 + c) * HW + gp];
    }
    __syncthreads();
    {   // GEMM2: out[d][p] -> B
        int p0 = (tid >> 4) << 2, d0 = (tid & 15) << 2;
        float s[4][4] = {};
        #pragma unroll 4
        for (int c = 0; c < 64; c++) {
            float4 vv = *(const float4*)(A + c * WSTR + p0);
            float4 av = *(const float4*)(C + c * WSTR + d0);
            float vr[4] = {vv.x, vv.y, vv.z, vv.w};
            float ar[4] = {av.x, av.y, av.z, av.w};
            #pragma unroll
            for (int i = 0; i < 4; i++)
                #pragma unroll
                for (int j = 0; j < 4; j++) s[i][j] += vr[i] * ar[j];
        }
        #pragma unroll
        for (int j = 0; j < 4; j++)
            *(float4*)(B + (d0 + j) * WSTR + p0) = make_float4(s[0][j], s[1][j], s[2][j], s[3][j]);
    }
    __syncthreads();
    {   // GEMM3: proj y[o][p] = sum_d Pw[d][o] * B[d][p]  -> C
        int o0 = (tid >> 4) << 2, p0 = (tid & 15) << 2;
        float s[4][4] = {};
        #pragma unroll 4
        for (int d = 0; d < 64; d++) {
            float4 wv = *(const float4*)(Pw + d * WSTR + o0);
            float4 bv = *(const float4*)(B + d * WSTR + p0);
            float wr[4] = {wv.x, wv.y, wv.z, wv.w};
            float br[4] = {bv.x, bv.y, bv.z, bv.w};
            #pragma unroll
            for (int i = 0; i < 4; i++)
                #pragma unroll
                for (int j = 0; j < 4; j++) s[i][j] += wr[i] * br[j];
        }
        #pragma unroll
        for (int i = 0; i < 4; i++)
            *(float4*)(C + (o0 + i) * WSTR + p0) = make_float4(s[i][0], s[i][1], s[i][2], s[i][3]);
    }
    __syncthreads();
    size_t obase = (size_t)b * 64 * HW;
    for (int e = tid; e < 4096; e += 256) {   // store with inverse roll (+4,+4)
        int p = e & 63, o = e >> 6;
        int gh = (((wy << 3) + (p >> 3)) + 4) & 127;
        int gw = (((wx << 3) + (p & 7)) + 4) & 127;
        out[obase + o * HW + (gh << 7) + gw] = C[o * WSTR + p];
    }
}

// ---------------- GSA: partial Gram sums (chunked) -------------------------------
__global__ void gsa_attn_part(const float* __restrict__ qkv, float* __restrict__ part)
{
    __shared__ float red[8][80];
    int bh = blockIdx.y;
    int b = bh >> 3, hd = bh & 7;
    int chunk = blockIdx.x;
    int tid = threadIdx.x;
    const float* qb = qkv + ((size_t)b * 192 + hd * 8) * HW;
    const float* kb = qkv + ((size_t)b * 192 + 64 + hd * 8) * HW;
    float dot[8][8] = {};
    float qn[8] = {}, kn[8] = {};
    int n0 = chunk * 2048;
    for (int n = n0 + tid; n < n0 + 2048; n += 256) {
        float qv[8], kv[8];
        #pragma unroll
        for (int i = 0; i < 8; i++) { qv[i] = qb[i * HW + n]; kv[i] = kb[i * HW + n]; }
        #pragma unroll
        for (int i = 0; i < 8; i++) { qn[i] += qv[i] * qv[i]; kn[i] += kv[i] * kv[i]; }
        #pragma unroll
        for (int i = 0; i < 8; i++)
            #pragma unroll
            for (int j = 0; j < 8; j++) dot[i][j] += qv[i] * kv[j];
    }
    int lane = tid & 31, w = tid >> 5;
    #pragma unroll
    for (int i = 0; i < 8; i++)
        #pragma unroll
        for (int j = 0; j < 8; j++) {
            float v = dot[i][j];
            #pragma unroll
            for (int off = 16; off; off >>= 1) v += __shfl_xor_sync(0xffffffffu, v, off);
            if (lane == 0) red[w][i * 8 + j] = v;
        }
    #pragma unroll
    for (int i = 0; i < 8; i++) {
        float v = qn[i];
        #pragma unroll
        for (int off = 16; off; off >>= 1) v += __shfl_xor_sync(0xffffffffu, v, off);
        if (lane == 0) red[w][64 + i] = v;
        float u = kn[i];
        #pragma unroll
        for (int off = 16; off; off >>= 1) u += __shfl_xor_sync(0xffffffffu, u, off);
        if (lane == 0) red[w][72 + i] = u;
    }
    __syncthreads();
    if (tid < 80) {
        float s = 0.f;
        #pragma unroll
        for (int w2 = 0; w2 < 8; w2++) s += red[w2][tid];
        part[((size_t)bh * 8 + chunk) * 80 + tid] = s;
    }
}

__global__ void gsa_attn_final(const float* __restrict__ part, float* __restrict__ attn,
                               const float* __restrict__ temp)
{
    __shared__ float fin[80];
    int bh = blockIdx.x, tid = threadIdx.x;
    if (tid < 80) {
        float s = 0.f;
        #pragma unroll
        for (int c = 0; c < 8; c++) s += part[((size_t)bh * 8 + c) * 80 + tid];
        fin[tid] = s;
    }
    __syncthreads();
    if (tid < 64) {
        int c = tid >> 3, d = tid & 7;
        float nq = fmaxf(sqrtf(fin[64 + c]), 1e-12f);
        float nk = fmaxf(sqrtf(fin[72 + d]), 1e-12f);
        attn[(size_t)bh * 64 + tid] = fmaxf(0.f, temp[0] * fin[tid] / (nq * nk));
    }
}

// ---------------- GSA: fold proj into attention matrix: M = f(pw, attn) ----------
// M[b][o][hd*8+d] = sum_c pw[o, c*8+hd] * attn[b,hd, c*8+d]
__global__ void gsa_makeM(const float* __restrict__ attn, const float* __restrict__ pw,
                          float* __restrict__ M)
{
    __shared__ float at[512];
    int b = blockIdx.x, tid = threadIdx.x;
    for (int e = tid; e < 512; e += 256) at[e] = attn[(size_t)b * 512 + e];
    __syncthreads();
    for (int t = 0; t < 16; t++) {
        int e = t * 256 + tid;
        int o = e >> 6, chp = e & 63;
        int hd = chp >> 3, d = chp & 7;
        float s = 0.f;
        #pragma unroll
        for (int c = 0; c < 8; c++)
            s += pw[(size_t)o * 64 + c * 8 + hd] * at[hd * 64 + c * 8 + d];
        M[(size_t)b * 4096 + e] = s;
    }
}

// ---------------- GSA: out = M @ v  (proj included) ------------------------------
__global__ void gsa_mv_kernel(const float* __restrict__ qkv, const float* __restrict__ M,
                              float* __restrict__ out)
{
    __shared__ float Ms[4096];
    int b = blockIdx.y, tid = threadIdx.x;
    for (int e = tid; e < 4096; e += 256) Ms[e] = M[(size_t)b * 4096 + e];
    __syncthreads();
    int n = blockIdx.x * 256 + tid;
    const float* vb = qkv + ((size_t)b * 192 + 128) * HW + n;
    float* ob = out + (size_t)b * 64 * HW + n;
    float vv[64];
    #pragma unroll
    for (int c = 0; c < 64; c++) vv[c] = vb[(size_t)c * HW];
    #pragma unroll
    for (int og = 0; og < 8; og++) {
        float acc[8] = {0.f,0.f,0.f,0.f,0.f,0.f,0.f,0.f};
        #pragma unroll
        for (int c = 0; c < 64; c++) {
            float v = vv[c];
            #pragma unroll
            for (int j = 0; j < 8; j++) acc[j] += Ms[(og * 8 + j) * 64 + c] * v;
        }
        #pragma unroll
        for (int j = 0; j < 8; j++) ob[(size_t)(og * 8 + j) * HW] = acc[j];
    }
}

// ---------------- launch ---------------------------------------------------------
extern "C" void kernel_launch(void* const* d_in, const int* in_sizes, int n_in,
                              void* d_out, int out_size)
{
    const float* x         = (const float*)d_in[0];
    const float* ln_s0_w   = (const float*)d_in[1];
    const float* ln_s0_b   = (const float*)d_in[2];
    const float* ln_s2_w   = (const float*)d_in[3];
    const float* ln_s2_b   = (const float*)d_in[4];
    const float* rsa_qkv_w = (const float*)d_in[5];
    const float* rsa_dw_w  = (const float*)d_in[6];
    const float* rsa_proj_w= (const float*)d_in[7];
    const float* rsa_temp  = (const float*)d_in[8];
    const float* ffs_in_w  = (const float*)d_in[9];
    const float* ffs_dw_w  = (const float*)d_in[10];
    const float* ffs_out_w = (const float*)d_in[11];
    const float* ln_c0_w   = (const float*)d_in[12];
    const float* ln_c0_b   = (const float*)d_in[13];
    const float* ln_c2_w   = (const float*)d_in[14];
    const float* ln_c2_b   = (const float*)d_in[15];
    const float* gsa_qkv_w = (const float*)d_in[16];
    const float* gsa_dw_w  = (const float*)d_in[17];
    const float* gsa_proj_w= (const float*)d_in[18];
    const float* gsa_temp  = (const float*)d_in[19];
    const float* ffc_in_w  = (const float*)d_in[20];
    const float* ffc_dw_w  = (const float*)d_in[21];
    const float* ffc_out_w = (const float*)d_in[22];
    float* outp = (float*)d_out;

    float *bufR, *bufX, *bufG, *big2, *attnb, *partb, *Mb;
    cudaGetSymbolAddress((void**)&bufR,  g_bufR);
    cudaGetSymbolAddress((void**)&bufX,  g_bufX);
    cudaGetSymbolAddress((void**)&bufG,  g_bufG);
    cudaGetSymbolAddress((void**)&big2,  g_big2);
    cudaGetSymbolAddress((void**)&attnb, g_attn);
    cudaGetSymbolAddress((void**)&partb, g_part);
    cudaGetSymbolAddress((void**)&Mb,    g_M);

    const int cdw_smem = (256 * XSTR + 4096 + 32 * COSTR + 256 + 256 + 32 + 32 + 288) * (int)sizeof(float);
    const int ctc_smem = (256 * XSTR + 8192) * (int)sizeof(float);
    const int rsa_smem = (4 * 64 * WSTR + 64) * (int)sizeof(float);
    cudaFuncSetAttribute(convdw_kernel, cudaFuncAttributeMaxDynamicSharedMemorySize, cdw_smem);
    cudaFuncSetAttribute(convtc_kernel, cudaFuncAttributeMaxDynamicSharedMemorySize, ctc_smem);
    cudaFuncSetAttribute(rsa_attn_kernel, cudaFuncAttributeMaxDynamicSharedMemorySize, rsa_smem);

    // ---- stage 1: RSA + spatial FFN ----
    convdw_kernel<<<dim3(6, 32, Bn), 256, cdw_smem>>>(x, nullptr, ln_s0_w, ln_s0_b, rsa_qkv_w, rsa_dw_w, big2, 192, 4);
    rsa_attn_kernel<<<Bn * 256, 256, rsa_smem>>>(big2, rsa_proj_w, bufR, rsa_temp);
    convdw_kernel<<<dim3(11, 32, Bn), 256, cdw_smem>>>(bufR, x, ln_s2_w, ln_s2_b, ffs_in_w, ffs_dw_w, big2, 340, 0);
    convtc_kernel<<<dim3(64, 1, Bn), 256, ctc_smem>>>(big2, ffs_out_w, bufX, bufR);

    // ---- stage 2: GSA + channel FFN ----
    convdw_kernel<<<dim3(6, 32, Bn), 256, cdw_smem>>>(bufX, nullptr, ln_c0_w, ln_c0_b, gsa_qkv_w, gsa_dw_w, big2, 192, 0);
    gsa_attn_part<<<dim3(8, 64), 256>>>(big2, partb);
    gsa_attn_final<<<64, 128>>>(partb, attnb, gsa_temp);
    gsa_makeM<<<Bn, 256>>>(attnb, gsa_proj_w, Mb);
    gsa_mv_kernel<<<dim3(64, Bn), 256>>>(big2, Mb, bufG);
    convdw_kernel<<<dim3(11, 32, Bn), 256, cdw_smem>>>(bufG, bufX, ln_c2_w, ln_c2_b, ffc_in_w, ffc_dw_w, big2, 340, 0);
    convtc_kernel<<<dim3(64, 1, Bn), 256, ctc_smem>>>(big2, ffc_out_w, outp, bufG);
}

// round 6
// speedup vs baseline: 1.5702x; 1.5702x over previous
#include <cuda_runtime.h>
#include <math.h>
#include <stdint.h>

#define HW    16384
#define Bn    8
#define HIDn  170
#define XSTR  68
#define WSTR  68

// ---------------- scratch (static device memory) ----------------
__device__ float g_bufR[Bn * 64 * HW];
__device__ float g_bufX[Bn * 64 * HW];
__device__ float g_bufG[Bn * 64 * HW];
__device__ float g_big1[Bn * 340 * HW];
__device__ float g_big2[Bn * 340 * HW];
__device__ float g_attn[Bn * 8 * 64];
__device__ float g_part[64 * 8 * 80];
__device__ float g_M[Bn * 64 * 64];

__device__ __forceinline__ float gelu_f(float x) {
    return 0.5f * x * (1.0f + erff(x * 0.70710678118654752f));
}
__device__ __forceinline__ uint32_t f2tf32(float x) {
    uint32_t r; asm("cvt.rna.tf32.f32 %0, %1;" : "=r"(r) : "f"(x)); return r;
}
__device__ __forceinline__ void ldsm4(uint32_t* a, uint32_t addr) {
    asm volatile("ldmatrix.sync.aligned.m8n8.x4.shared.b16 {%0,%1,%2,%3}, [%4];"
        : "=r"(a[0]), "=r"(a[1]), "=r"(a[2]), "=r"(a[3]) : "r"(addr));
}
__device__ __forceinline__ void mma_tf32(float* d, const uint32_t* a, uint32_t b0, uint32_t b1) {
    asm volatile("mma.sync.aligned.m16n8k8.row.col.f32.tf32.tf32.f32 "
        "{%0,%1,%2,%3}, {%4,%5,%6,%7}, {%8,%9}, {%0,%1,%2,%3};"
        : "+f"(d[0]), "+f"(d[1]), "+f"(d[2]), "+f"(d[3])
        : "r"(a[0]), "r"(a[1]), "r"(a[2]), "r"(a[3]), "r"(b0), "r"(b1));
}

// =================================================================
// LN-fused tensor-core conv1x1 (Cin=64). Stages X ONCE, loops over
// out-tiles of 64 (Cout up to 384) reusing the staged activations.
// tile: 256 px x 64 out per pass, 256 thr (8 warps, warp=32px)
// =================================================================
__global__ void __launch_bounds__(256, 2)
convtc_kernel(const float* __restrict__ in, const float* __restrict__ addp,
              const float* __restrict__ lnw, const float* __restrict__ lnb,
              const float* __restrict__ wt, float* __restrict__ out,
              int Cout, int shift)
{
    extern __shared__ float sm[];
    float* Xh   = sm;              // [256][68]
    float* BF   = sm + 256 * XSTR; // [8kb][8n8][32][4]
    float* mu_s = BF + 8192;       // [256]
    float* rs_s = mu_s + 256;      // [256]
    float* sg_s = rs_s + 256;      // [64]
    float* sb_s = sg_s + 64;       // [64]

    int b = blockIdx.z, p0 = blockIdx.x * 256;
    int tid = threadIdx.x, warp = tid >> 5, lane = tid & 31;
    const float* inb = in + (size_t)b * 64 * HW;
    const float* adb = addp ? addp + (size_t)b * 64 * HW : nullptr;

    int p = p0 + tid, ip = p;
    if (shift) {
        int hh = ((p >> 7) + shift) & 127, ww = ((p & 127) + shift) & 127;
        ip = (hh << 7) | ww;
    }
    // ---- stage X once + LN stats ----
    float s_sum = 0.f, s_sq = 0.f;
    #pragma unroll
    for (int j4 = 0; j4 < 16; j4++) {
        float v4[4];
        #pragma unroll
        for (int jj = 0; jj < 4; jj++) {
            int c = j4 * 4 + jj;
            float v = inb[(size_t)c * HW + ip];
            if (adb) v += adb[(size_t)c * HW + ip];
            s_sum += v; s_sq += v * v;
            v4[jj] = __uint_as_float(f2tf32(v));
        }
        *(float4*)&Xh[tid * XSTR + j4 * 4] = make_float4(v4[0], v4[1], v4[2], v4[3]);
    }
    {
        float m = s_sum * 0.015625f;
        float var = s_sq * 0.015625f - m * m;
        mu_s[tid] = m;
        rs_s[tid] = rsqrtf(fmaxf(var, 0.f) + 1e-5f);
    }

    int ntile = (Cout + 63) >> 6;
    for (int t = 0; t < ntile; t++) {
        __syncthreads();   // X/mu ready (first iter) + BF safe to overwrite
        int o0 = t << 6;
        // ---- stage W fragments for this out-tile (hi/lo tf32 split) ----
        #pragma unroll
        for (int i = 0; i < 16; i++) {
            int e = i * 256 + tid;
            int o = e >> 6, k = e & 63;
            int og = o0 + o;
            float wv = (og < Cout) ? wt[(size_t)og * 64 + k] * lnw[k] : 0.f;
            uint32_t whb = f2tf32(wv);
            float wlo = wv - __uint_as_float(whb);
            uint32_t wlb = f2tf32(wlo);
            int kb = k >> 3, kw = k & 7, n8 = o >> 3, nn = o & 7;
            float* dst = &BF[((kb * 8 + n8) * 32 + nn * 4 + (kw & 3)) * 4];
            dst[kw >> 2]       = __uint_as_float(whb);
            dst[(kw >> 2) + 2] = __uint_as_float(wlb);
        }
        if (tid < 64) {
            float sg = 0.f, sb = 0.f;
            int og = o0 + tid;
            if (og < Cout) {
                const float* wr = wt + (size_t)og * 64;
                #pragma unroll 8
                for (int k = 0; k < 64; k++) { sg += wr[k] * lnw[k]; sb += wr[k] * lnb[k]; }
            }
            sg_s[tid] = sg; sb_s[tid] = sb;
        }
        __syncthreads();

        // ---- tensor GEMM ----
        float accD[2][8][4] = {};
        uint32_t xbase = (uint32_t)__cvta_generic_to_shared(Xh);
        int r = lane & 7, madd8 = (lane >> 3) & 1, gsel = lane >> 4;
        uint32_t a_off0 = xbase + (((warp * 32) + r + madd8 * 8) * XSTR + gsel * 4) * 4;
        #pragma unroll
        for (int kb = 0; kb < 8; kb++) {
            uint32_t A0[4], A1[4];
            uint32_t addr0 = a_off0 + kb * 32;
            ldsm4(A0, addr0);
            ldsm4(A1, addr0 + 16 * XSTR * 4);
            const float4* bfk = (const float4*)&BF[(kb * 8) * 32 * 4];
            #pragma unroll
            for (int n8 = 0; n8 < 8; n8++) {
                float4 bv = bfk[n8 * 32 + lane];
                uint32_t bh0 = __float_as_uint(bv.x), bh1 = __float_as_uint(bv.y);
                uint32_t bl0 = __float_as_uint(bv.z), bl1 = __float_as_uint(bv.w);
                mma_tf32(accD[0][n8], A0, bh0, bh1);
                mma_tf32(accD[0][n8], A0, bl0, bl1);
                mma_tf32(accD[1][n8], A1, bh0, bh1);
                mma_tf32(accD[1][n8], A1, bl0, bl1);
            }
        }
        // ---- epilogue (LN transform) ----
        int gq = lane >> 2, oq = (lane & 3) * 2;
        #pragma unroll
        for (int tt = 0; tt < 2; tt++) {
            int pxa = warp * 32 + tt * 16 + gq;
            int pxb = pxa + 8;
            float mua = mu_s[pxa], rsa_ = rs_s[pxa];
            float mub = mu_s[pxb], rsb = rs_s[pxb];
            #pragma unroll
            for (int n8 = 0; n8 < 8; n8++) {
                #pragma unroll
                for (int q = 0; q < 2; q++) {
                    int ol = n8 * 8 + oq + q;
                    int og = o0 + ol;
                    if (og < Cout) {
                        float sg = sg_s[ol], sb = sb_s[ol];
                        float v0 = rsa_ * (accD[tt][n8][q]     - mua * sg) + sb;
                        float v1 = rsb  * (accD[tt][n8][q + 2] - mub * sg) + sb;
                        size_t obase = ((size_t)b * Cout + og) * HW + p0;
                        out[obase + pxa] = v0;
                        out[obase + pxb] = v1;
                    }
                }
            }
        }
    }
}

// =================================================================
// gated tensor-core conv (Cin=170 phys 340): 128-px tiles, occ 3
// =================================================================
__global__ void __launch_bounds__(256, 3)
convgate_kernel(const float* __restrict__ in, const float* __restrict__ wt,
                float* __restrict__ out, const float* __restrict__ resid)
{
    extern __shared__ float sm[];
    float* Xh = sm;            // [128][68]
    float* BF = sm + 128 * XSTR;

    int b = blockIdx.z, p0 = blockIdx.x * 128;
    int tid = threadIdx.x, warp = tid >> 5, lane = tid & 31;
    int px = tid & 127, half = tid >> 7;
    int ip = p0 + px;
    const float* inb = in + (size_t)b * 340 * HW;

    float acc[8][4] = {};
    const int kbs[3] = {8, 8, 6};
    for (int ch = 0; ch < 3; ch++) {
        if (ch) __syncthreads();
        int c0 = ch * 64;
        int nkb = kbs[ch];
        // stage X: 2 threads per px, 32 channels each
        #pragma unroll
        for (int j4 = 0; j4 < 8; j4++) {
            float v4[4];
            #pragma unroll
            for (int jj = 0; jj < 4; jj++) {
                int kloc = half * 32 + j4 * 4 + jj;
                int c = c0 + kloc;
                float v = 0.f;
                if (c < HIDn) {
                    float a = inb[(size_t)c * HW + ip];
                    float g = inb[(size_t)(c + HIDn) * HW + ip];
                    v = gelu_f(a) * g;
                }
                v4[jj] = __uint_as_float(f2tf32(v));
            }
            *(float4*)&Xh[px * XSTR + half * 32 + j4 * 4] = make_float4(v4[0], v4[1], v4[2], v4[3]);
        }
        // stage BF
        int kw8 = nkb * 8;
        int tot = 64 * kw8;
        for (int e = tid; e < tot; e += 256) {
            int o = e / kw8;
            int k = e - o * kw8;
            int kg = c0 + k;
            float wv = (kg < HIDn) ? wt[(size_t)o * HIDn + kg] : 0.f;
            uint32_t whb = f2tf32(wv);
            float wlo = wv - __uint_as_float(whb);
            uint32_t wlb = f2tf32(wlo);
            int kb = k >> 3, kw = k & 7, n8 = o >> 3, nn = o & 7;
            float* dst = &BF[((kb * 8 + n8) * 32 + nn * 4 + (kw & 3)) * 4];
            dst[kw >> 2]       = __uint_as_float(whb);
            dst[(kw >> 2) + 2] = __uint_as_float(wlb);
        }
        __syncthreads();
        // GEMM: warp = 16 px x 64 out
        uint32_t xbase = (uint32_t)__cvta_generic_to_shared(Xh);
        int r = lane & 7, madd8 = (lane >> 3) & 1, gsel = lane >> 4;
        uint32_t a_off0 = xbase + (((warp * 16) + r + madd8 * 8) * XSTR + gsel * 4) * 4;
        #pragma unroll 2
        for (int kb = 0; kb < nkb; kb++) {
            uint32_t A0[4];
            ldsm4(A0, a_off0 + kb * 32);
            const float4* bfk = (const float4*)&BF[(kb * 8) * 32 * 4];
            #pragma unroll
            for (int n8 = 0; n8 < 8; n8++) {
                float4 bv = bfk[n8 * 32 + lane];
                uint32_t bh0 = __float_as_uint(bv.x), bh1 = __float_as_uint(bv.y);
                uint32_t bl0 = __float_as_uint(bv.z), bl1 = __float_as_uint(bv.w);
                mma_tf32(acc[n8], A0, bh0, bh1);
                mma_tf32(acc[n8], A0, bl0, bl1);
            }
        }
    }
    // epilogue: + resid
    int gq = lane >> 2, oq = (lane & 3) * 2;
    int pxa = warp * 16 + gq, pxb = pxa + 8;
    #pragma unroll
    for (int n8 = 0; n8 < 8; n8++) {
        #pragma unroll
        for (int q = 0; q < 2; q++) {
            int og = n8 * 8 + oq + q;
            size_t obase = ((size_t)b * 64 + og) * HW + p0;
            out[obase + pxa] = acc[n8][q]     + resid[obase + pxa];
            out[obase + pxb] = acc[n8][q + 2] + resid[obase + pxb];
        }
    }
}

// ---------------- depthwise 3x3 conv, zero padding, 4 px/thread ----------------
__global__ void dwconv_kernel(const float* __restrict__ in, const float* __restrict__ wt,
                              float* __restrict__ out, int Ch)
{
    int c = blockIdx.y, b = blockIdx.z;
    int p = (blockIdx.x * 256 + threadIdx.x) << 2;
    int h = p >> 7, w0 = p & 127;
    const float* ib = in + ((size_t)b * Ch + c) * HW;
    const float* wc = wt + c * 9;
    float acc[4] = {0.f, 0.f, 0.f, 0.f};
    #pragma unroll
    for (int dy = -1; dy <= 1; dy++) {
        int hh = h + dy;
        if ((unsigned)hh > 127u) continue;
        const float* row = ib + (hh << 7);
        float4 mid = *(const float4*)(row + w0);
        float r0 = (w0 > 0)   ? row[w0 - 1] : 0.f;
        float r5 = (w0 < 124) ? row[w0 + 4] : 0.f;
        float r[6] = {r0, mid.x, mid.y, mid.z, mid.w, r5};
        float wa = wc[(dy + 1) * 3 + 0], wb = wc[(dy + 1) * 3 + 1], wcc = wc[(dy + 1) * 3 + 2];
        #pragma unroll
        for (int j = 0; j < 4; j++)
            acc[j] += wa * r[j] + wb * r[j + 1] + wcc * r[j + 2];
    }
    *(float4*)(out + ((size_t)b * Ch + c) * HW + p) = make_float4(acc[0], acc[1], acc[2], acc[3]);
}

// =================================================================
// RSA window attention + fused proj conv + inverse roll
// =================================================================
__global__ void __launch_bounds__(256, 3)
rsa_attn_kernel(const float* __restrict__ qkv, const float* __restrict__ pw,
                float* __restrict__ out, const float* __restrict__ temp)
{
    extern __shared__ float sm[];
    float* A   = sm;
    float* B   = sm + 64 * WSTR;
    float* C   = sm + 2 * 64 * WSTR;
    float* Pw  = sm + 3 * 64 * WSTR;
    float* inv = Pw + 64 * WSTR;
    int blk = blockIdx.x;
    int b = blk >> 8, win = blk & 255;
    int wy = win >> 4, wx = win & 15;
    int tid = threadIdx.x;
    size_t qbase = (size_t)b * 192 * HW;

    for (int e = tid; e < 4096; e += 256) {
        int p = e & 63, c = e >> 6;
        int gp = (((wy << 3) + (p >> 3)) << 7) | ((wx << 3) + (p & 7));
        A[p * WSTR + c] = qkv[qbase + c * HW + gp];
        B[p * WSTR + c] = qkv[qbase + (64 + c) * HW + gp];
        Pw[(e & 63) * WSTR + (e >> 6)] = pw[e];
    }
    __syncthreads();
    if (tid < 64) {
        int p = tid;
        float nq = 0.f, nk = 0.f;
        #pragma unroll
        for (int c = 0; c < 64; c++) {
            float a = A[p * WSTR + c]; nq += a * a;
            float bb = B[p * WSTR + c]; nk += bb * bb;
        }
        inv[p] = 1.0f / (fmaxf(sqrtf(nq), 1e-12f) * fmaxf(sqrtf(nk), 1e-12f));
    }
    __syncthreads();
    for (int e4 = tid; e4 < 1024; e4 += 256) {
        int p = e4 >> 4, c4 = e4 & 15;
        float iv = inv[p];
        float4 v = ((float4*)B)[p * (WSTR / 4) + c4];
        v.x *= iv; v.y *= iv; v.z *= iv; v.w *= iv;
        ((float4*)B)[p * (WSTR / 4) + c4] = v;
    }
    __syncthreads();
    float tscale = temp[0];
    {   // GEMM1: attn
        int c0 = (tid >> 4) << 2, d0 = (tid & 15) << 2;
        float s[4][4] = {};
        #pragma unroll 4
        for (int p = 0; p < 64; p++) {
            float4 qv = *(const float4*)(A + p * WSTR + c0);
            float4 kv = *(const float4*)(B + p * WSTR + d0);
            float qr[4] = {qv.x, qv.y, qv.z, qv.w};
            float kr[4] = {kv.x, kv.y, kv.z, kv.w};
            #pragma unroll
            for (int i = 0; i < 4; i++)
                #pragma unroll
                for (int j = 0; j < 4; j++) s[i][j] += qr[i] * kr[j];
        }
        #pragma unroll
        for (int i = 0; i < 4; i++)
            *(float4*)(C + (c0 + i) * WSTR + d0) =
                make_float4(fmaxf(0.f, tscale * s[i][0]), fmaxf(0.f, tscale * s[i][1]),
                            fmaxf(0.f, tscale * s[i][2]), fmaxf(0.f, tscale * s[i][3]));
    }
    __syncthreads();
    for (int e = tid; e < 4096; e += 256) {
        int p = e & 63, c = e >> 6;
        int gp = (((wy << 3) + (p >> 3)) << 7) | ((wx << 3) + (p & 7));
        A[c * WSTR + p] = qkv[qbase + (128 + c) * HW + gp];
    }
    __syncthreads();
    {   // GEMM2: out[d][p]
        int p0 = (tid >> 4) << 2, d0 = (tid & 15) << 2;
        float s[4][4] = {};
        #pragma unroll 4
        for (int c = 0; c < 64; c++) {
            float4 vv = *(const float4*)(A + c * WSTR + p0);
            float4 av = *(const float4*)(C + c * WSTR + d0);
            float vr[4] = {vv.x, vv.y, vv.z, vv.w};
            float ar[4] = {av.x, av.y, av.z, av.w};
            #pragma unroll
            for (int i = 0; i < 4; i++)
                #pragma unroll
                for (int j = 0; j < 4; j++) s[i][j] += vr[i] * ar[j];
        }
        #pragma unroll
        for (int j = 0; j < 4; j++)
            *(float4*)(B + (d0 + j) * WSTR + p0) = make_float4(s[0][j], s[1][j], s[2][j], s[3][j]);
    }
    __syncthreads();
    {   // GEMM3: proj
        int o0 = (tid >> 4) << 2, p0 = (tid & 15) << 2;
        float s[4][4] = {};
        #pragma unroll 4
        for (int d = 0; d < 64; d++) {
            float4 wv = *(const float4*)(Pw + d * WSTR + o0);
            float4 bv = *(const float4*)(B + d * WSTR + p0);
            float wr[4] = {wv.x, wv.y, wv.z, wv.w};
            float br[4] = {bv.x, bv.y, bv.z, bv.w};
            #pragma unroll
            for (int i = 0; i < 4; i++)
                #pragma unroll
                for (int j = 0; j < 4; j++) s[i][j] += wr[i] * br[j];
        }
        #pragma unroll
        for (int i = 0; i < 4; i++)
            *(float4*)(C + (o0 + i) * WSTR + p0) = make_float4(s[i][0], s[i][1], s[i][2], s[i][3]);
    }
    __syncthreads();
    size_t obase = (size_t)b * 64 * HW;
    for (int e = tid; e < 4096; e += 256) {
        int p = e & 63, o = e >> 6;
        int gh = (((wy << 3) + (p >> 3)) + 4) & 127;
        int gw = (((wx << 3) + (p & 7)) + 4) & 127;
        out[obase + o * HW + (gh << 7) + gw] = C[o * WSTR + p];
    }
}

// ---------------- GSA: partial Gram sums (chunked) -------------------------------
__global__ void gsa_attn_part(const float* __restrict__ qkv, float* __restrict__ part)
{
    __shared__ float red[8][80];
    int bh = blockIdx.y;
    int b = bh >> 3, hd = bh & 7;
    int chunk = blockIdx.x;
    int tid = threadIdx.x;
    const float* qb = qkv + ((size_t)b * 192 + hd * 8) * HW;
    const float* kb = qkv + ((size_t)b * 192 + 64 + hd * 8) * HW;
    float dot[8][8] = {};
    float qn[8] = {}, kn[8] = {};
    int n0 = chunk * 2048;
    for (int n = n0 + tid; n < n0 + 2048; n += 256) {
        float qv[8], kv[8];
        #pragma unroll
        for (int i = 0; i < 8; i++) { qv[i] = qb[i * HW + n]; kv[i] = kb[i * HW + n]; }
        #pragma unroll
        for (int i = 0; i < 8; i++) { qn[i] += qv[i] * qv[i]; kn[i] += kv[i] * kv[i]; }
        #pragma unroll
        for (int i = 0; i < 8; i++)
            #pragma unroll
            for (int j = 0; j < 8; j++) dot[i][j] += qv[i] * kv[j];
    }
    int lane = tid & 31, w = tid >> 5;
    #pragma unroll
    for (int i = 0; i < 8; i++)
        #pragma unroll
        for (int j = 0; j < 8; j++) {
            float v = dot[i][j];
            #pragma unroll
            for (int off = 16; off; off >>= 1) v += __shfl_xor_sync(0xffffffffu, v, off);
            if (lane == 0) red[w][i * 8 + j] = v;
        }
    #pragma unroll
    for (int i = 0; i < 8; i++) {
        float v = qn[i];
        #pragma unroll
        for (int off = 16; off; off >>= 1) v += __shfl_xor_sync(0xffffffffu, v, off);
        if (lane == 0) red[w][64 + i] = v;
        float u = kn[i];
        #pragma unroll
        for (int off = 16; off; off >>= 1) u += __shfl_xor_sync(0xffffffffu, u, off);
        if (lane == 0) red[w][72 + i] = u;
    }
    __syncthreads();
    if (tid < 80) {
        float s = 0.f;
        #pragma unroll
        for (int w2 = 0; w2 < 8; w2++) s += red[w2][tid];
        part[((size_t)bh * 8 + chunk) * 80 + tid] = s;
    }
}

__global__ void gsa_attn_final(const float* __restrict__ part, float* __restrict__ attn,
                               const float* __restrict__ temp)
{
    __shared__ float fin[80];
    int bh = blockIdx.x, tid = threadIdx.x;
    if (tid < 80) {
        float s = 0.f;
        #pragma unroll
        for (int c = 0; c < 8; c++) s += part[((size_t)bh * 8 + c) * 80 + tid];
        fin[tid] = s;
    }
    __syncthreads();
    if (tid < 64) {
        int c = tid >> 3, d = tid & 7;
        float nq = fmaxf(sqrtf(fin[64 + c]), 1e-12f);
        float nk = fmaxf(sqrtf(fin[72 + d]), 1e-12f);
        attn[(size_t)bh * 64 + tid] = fmaxf(0.f, temp[0] * fin[tid] / (nq * nk));
    }
}

// ---------------- GSA: fold proj into attention matrix -------------------------
__global__ void gsa_makeM(const float* __restrict__ attn, const float* __restrict__ pw,
                          float* __restrict__ M)
{
    __shared__ float at[512];
    int b = blockIdx.x, tid = threadIdx.x;
    for (int e = tid; e < 512; e += 256) at[e] = attn[(size_t)b * 512 + e];
    __syncthreads();
    for (int t = 0; t < 16; t++) {
        int e = t * 256 + tid;
        int o = e >> 6, chp = e & 63;
        int hd = chp >> 3, d = chp & 7;
        float s = 0.f;
        #pragma unroll
        for (int c = 0; c < 8; c++)
            s += pw[(size_t)o * 64 + c * 8 + hd] * at[hd * 64 + c * 8 + d];
        M[(size_t)b * 4096 + e] = s;
    }
}

// ---------------- GSA: out = M @ v (proj included) ------------------------------
__global__ void gsa_mv_kernel(const float* __restrict__ qkv, const float* __restrict__ M,
                              float* __restrict__ out)
{
    __shared__ float Ms[4096];
    int b = blockIdx.y, tid = threadIdx.x;
    for (int e = tid; e < 4096; e += 256) Ms[e] = M[(size_t)b * 4096 + e];
    __syncthreads();
    int n = blockIdx.x * 256 + tid;
    const float* vb = qkv + ((size_t)b * 192 + 128) * HW + n;
    float* ob = out + (size_t)b * 64 * HW + n;
    float vv[64];
    #pragma unroll
    for (int c = 0; c < 64; c++) vv[c] = vb[(size_t)c * HW];
    #pragma unroll
    for (int og = 0; og < 8; og++) {
        float acc[8] = {0.f,0.f,0.f,0.f,0.f,0.f,0.f,0.f};
        #pragma unroll
        for (int c = 0; c < 64; c++) {
            float v = vv[c];
            #pragma unroll
            for (int j = 0; j < 8; j++) acc[j] += Ms[(og * 8 + j) * 64 + c] * v;
        }
        #pragma unroll
        for (int j = 0; j < 8; j++) ob[(size_t)(og * 8 + j) * HW] = acc[j];
    }
}

// ---------------- launch ---------------------------------------------------------
extern "C" void kernel_launch(void* const* d_in, const int* in_sizes, int n_in,
                              void* d_out, int out_size)
{
    const float* x         = (const float*)d_in[0];
    const float* ln_s0_w   = (const float*)d_in[1];
    const float* ln_s0_b   = (const float*)d_in[2];
    const float* ln_s2_w   = (const float*)d_in[3];
    const float* ln_s2_b   = (const float*)d_in[4];
    const float* rsa_qkv_w = (const float*)d_in[5];
    const float* rsa_dw_w  = (const float*)d_in[6];
    const float* rsa_proj_w= (const float*)d_in[7];
    const float* rsa_temp  = (const float*)d_in[8];
    const float* ffs_in_w  = (const float*)d_in[9];
    const float* ffs_dw_w  = (const float*)d_in[10];
    const float* ffs_out_w = (const float*)d_in[11];
    const float* ln_c0_w   = (const float*)d_in[12];
    const float* ln_c0_b   = (const float*)d_in[13];
    const float* ln_c2_w   = (const float*)d_in[14];
    const float* ln_c2_b   = (const float*)d_in[15];
    const float* gsa_qkv_w = (const float*)d_in[16];
    const float* gsa_dw_w  = (const float*)d_in[17];
    const float* gsa_proj_w= (const float*)d_in[18];
    const float* gsa_temp  = (const float*)d_in[19];
    const float* ffc_in_w  = (const float*)d_in[20];
    const float* ffc_dw_w  = (const float*)d_in[21];
    const float* ffc_out_w = (const float*)d_in[22];
    float* outp = (float*)d_out;

    float *bufR, *bufX, *bufG, *big1, *big2, *attnb, *partb, *Mb;
    cudaGetSymbolAddress((void**)&bufR,  g_bufR);
    cudaGetSymbolAddress((void**)&bufX,  g_bufX);
    cudaGetSymbolAddress((void**)&bufG,  g_bufG);
    cudaGetSymbolAddress((void**)&big1,  g_big1);
    cudaGetSymbolAddress((void**)&big2,  g_big2);
    cudaGetSymbolAddress((void**)&attnb, g_attn);
    cudaGetSymbolAddress((void**)&partb, g_part);
    cudaGetSymbolAddress((void**)&Mb,    g_M);

    const int ctc_smem = (256 * XSTR + 8192 + 256 + 256 + 64 + 64) * (int)sizeof(float);
    const int cg_smem  = (128 * XSTR + 8192) * (int)sizeof(float);
    const int rsa_smem = (4 * 64 * WSTR + 64) * (int)sizeof(float);
    cudaFuncSetAttribute(convtc_kernel, cudaFuncAttributeMaxDynamicSharedMemorySize, ctc_smem);
    cudaFuncSetAttribute(convgate_kernel, cudaFuncAttributeMaxDynamicSharedMemorySize, cg_smem);
    cudaFuncSetAttribute(rsa_attn_kernel, cudaFuncAttributeMaxDynamicSharedMemorySize, rsa_smem);

    // ---- stage 1: RSA + spatial FFN ----
    convtc_kernel<<<dim3(64, 1, Bn), 256, ctc_smem>>>(x, nullptr, ln_s0_w, ln_s0_b, rsa_qkv_w, big1, 192, 4);
    dwconv_kernel<<<dim3(16, 192, Bn), 256>>>(big1, rsa_dw_w, big2, 192);
    rsa_attn_kernel<<<Bn * 256, 256, rsa_smem>>>(big2, rsa_proj_w, bufR, rsa_temp);
    convtc_kernel<<<dim3(64, 1, Bn), 256, ctc_smem>>>(bufR, x, ln_s2_w, ln_s2_b, ffs_in_w, big1, 340, 0);
    dwconv_kernel<<<dim3(16, 340, Bn), 256>>>(big1, ffs_dw_w, big2, 340);
    convgate_kernel<<<dim3(128, 1, Bn), 256, cg_smem>>>(big2, ffs_out_w, bufX, bufR);

    // ---- stage 2: GSA + channel FFN ----
    convtc_kernel<<<dim3(64, 1, Bn), 256, ctc_smem>>>(bufX, nullptr, ln_c0_w, ln_c0_b, gsa_qkv_w, big1, 192, 0);
    dwconv_kernel<<<dim3(16, 192, Bn), 256>>>(big1, gsa_dw_w, big2, 192);
    gsa_attn_part<<<dim3(8, 64), 256>>>(big2, partb);
    gsa_attn_final<<<64, 128>>>(partb, attnb, gsa_temp);
    gsa_makeM<<<Bn, 256>>>(attnb, gsa_proj_w, Mb);
    gsa_mv_kernel<<<dim3(64, Bn), 256>>>(big2, Mb, bufG);
    convtc_kernel<<<dim3(64, 1, Bn), 256, ctc_smem>>>(bufG, bufX, ln_c2_w, ln_c2_b, ffc_in_w, big1, 340, 0);
    dwconv_kernel<<<dim3(16, 340, Bn), 256>>>(big1, ffc_dw_w, big2, 340);
    convgate_kernel<<<dim3(128, 1, Bn), 256, cg_smem>>>(big2, ffc_out_w, outp, bufG);
}

// round 7
// speedup vs baseline: 1.7213x; 1.0963x over previous
#include <cuda_runtime.h>
#include <math.h>
#include <stdint.h>

#define HW    16384
#define Bn    8
#define HIDn  170
#define XSTR  68      // floats per X row = 272B = 17 x 16B granules (conflict-free)
#define WSTR  68

// ---------------- scratch (static device memory) ----------------
__device__ float g_bufR[Bn * 64 * HW];
__device__ float g_bufX[Bn * 64 * HW];
__device__ float g_bufG[Bn * 64 * HW];
__device__ float g_big1[Bn * 340 * HW];
__device__ float g_big2[Bn * 340 * HW];
__device__ float g_attn[Bn * 8 * 64];
__device__ float g_part[64 * 8 * 80];
__device__ float g_M[Bn * 64 * 64];

__device__ __forceinline__ float gelu_f(float x) {
    return 0.5f * x * (1.0f + erff(x * 0.70710678118654752f));
}
__device__ __forceinline__ uint16_t bf16b(float x) {
    uint16_t r; asm("cvt.rn.bf16.f32 %0, %1;" : "=h"(r) : "f"(x)); return r;
}
__device__ __forceinline__ uint32_t pk2(uint16_t lo, uint16_t hi) {
    return (uint32_t)lo | ((uint32_t)hi << 16);
}
__device__ __forceinline__ void bsplit(float v, uint16_t& h, uint16_t& l) {
    h = bf16b(v);
    float hf = __uint_as_float((uint32_t)h << 16);
    l = bf16b(v - hf);
}
__device__ __forceinline__ void ldsm4(uint32_t* a, uint32_t addr) {
    asm volatile("ldmatrix.sync.aligned.m8n8.x4.shared.b16 {%0,%1,%2,%3}, [%4];"
        : "=r"(a[0]), "=r"(a[1]), "=r"(a[2]), "=r"(a[3]) : "r"(addr));
}
__device__ __forceinline__ void mma_bf16(float* d, const uint32_t* a, uint32_t b0, uint32_t b1) {
    asm volatile("mma.sync.aligned.m16n8k16.row.col.f32.bf16.bf16.f32 "
        "{%0,%1,%2,%3}, {%4,%5,%6,%7}, {%8,%9}, {%0,%1,%2,%3};"
        : "+f"(d[0]), "+f"(d[1]), "+f"(d[2]), "+f"(d[3])
        : "r"(a[0]), "r"(a[1]), "r"(a[2]), "r"(a[3]), "r"(b0), "r"(b1));
}

// =================================================================
// LN-fused tensor-core conv1x1 (Cin=64), bf16 3-term split.
// X row (272B): hi bf16 ch0-63 at [0,128), lo at [144,272).
// Stages X ONCE, loops out-tiles of 64. 256px x 64out, 8 warps.
// =================================================================
__global__ void __launch_bounds__(256, 2)
convtc_kernel(const float* __restrict__ in, const float* __restrict__ addp,
              const float* __restrict__ lnw, const float* __restrict__ lnb,
              const float* __restrict__ wt, float* __restrict__ out,
              int Cout, int shift)
{
    extern __shared__ float sm[];
    float* Xh   = sm;                         // 256 x 68 floats (272B rows)
    uint4* BF   = (uint4*)(sm + 256 * XSTR);  // [4kb][8n8][32] uint4 = 16KB
    float* mu_s = sm + 256 * XSTR + 4096;     // [256]
    float* rs_s = mu_s + 256;                 // [256]
    float* sg_s = rs_s + 256;                 // [64]
    float* sb_s = sg_s + 64;                  // [64]

    int b = blockIdx.z, p0 = blockIdx.x * 256;
    int tid = threadIdx.x, warp = tid >> 5, lane = tid & 31;
    const float* inb = in + (size_t)b * 64 * HW;
    const float* adb = addp ? addp + (size_t)b * 64 * HW : nullptr;

    int p = p0 + tid, ip = p;
    if (shift) {
        int hh = ((p >> 7) + shift) & 127, ww = ((p & 127) + shift) & 127;
        ip = (hh << 7) | ww;
    }
    // ---- stage X once (bf16 hi/lo) + LN stats ----
    float s_sum = 0.f, s_sq = 0.f;
    char* xrow = (char*)Xh + tid * 272;
    #pragma unroll
    for (int j8 = 0; j8 < 8; j8++) {
        uint16_t hb[8], lb[8];
        #pragma unroll
        for (int jj = 0; jj < 8; jj++) {
            int c = j8 * 8 + jj;
            float v = inb[(size_t)c * HW + ip];
            if (adb) v += adb[(size_t)c * HW + ip];
            s_sum += v; s_sq += v * v;
            bsplit(v, hb[jj], lb[jj]);
        }
        *(uint4*)(xrow + j8 * 16) =
            make_uint4(pk2(hb[0], hb[1]), pk2(hb[2], hb[3]), pk2(hb[4], hb[5]), pk2(hb[6], hb[7]));
        *(uint4*)(xrow + 144 + j8 * 16) =
            make_uint4(pk2(lb[0], lb[1]), pk2(lb[2], lb[3]), pk2(lb[4], lb[5]), pk2(lb[6], lb[7]));
    }
    {
        float m = s_sum * 0.015625f;
        float var = s_sq * 0.015625f - m * m;
        mu_s[tid] = m;
        rs_s[tid] = rsqrtf(fmaxf(var, 0.f) + 1e-5f);
    }

    int ntile = (Cout + 63) >> 6;
    for (int t = 0; t < ntile; t++) {
        __syncthreads();
        int o0 = t << 6;
        // ---- stage W fragments (bf16 hi/lo, gamma folded) ----
        #pragma unroll
        for (int i = 0; i < 4; i++) {
            int e = i * 256 + tid;
            int kb = e >> 8, rem = e & 255;
            int n8 = rem >> 5, ln2 = rem & 31;
            int g = ln2 >> 2, t2 = ln2 & 3;
            int og = o0 + n8 * 8 + g;
            int kbase = kb * 16;
            float w0 = 0.f, w1 = 0.f, w2 = 0.f, w3 = 0.f;
            if (og < Cout) {
                const float* wr = wt + (size_t)og * 64 + kbase;
                w0 = wr[2 * t2]     * lnw[kbase + 2 * t2];
                w1 = wr[2 * t2 + 1] * lnw[kbase + 2 * t2 + 1];
                w2 = wr[2 * t2 + 8] * lnw[kbase + 2 * t2 + 8];
                w3 = wr[2 * t2 + 9] * lnw[kbase + 2 * t2 + 9];
            }
            uint16_t h0, l0, h1, l1, h2, l2, h3, l3;
            bsplit(w0, h0, l0); bsplit(w1, h1, l1);
            bsplit(w2, h2, l2); bsplit(w3, h3, l3);
            BF[(kb * 8 + n8) * 32 + ln2] =
                make_uint4(pk2(h0, h1), pk2(h2, h3), pk2(l0, l1), pk2(l2, l3));
        }
        if (tid < 64) {
            float sg = 0.f, sb = 0.f;
            int og = o0 + tid;
            if (og < Cout) {
                const float* wr = wt + (size_t)og * 64;
                #pragma unroll 8
                for (int k = 0; k < 64; k++) { sg += wr[k] * lnw[k]; sb += wr[k] * lnb[k]; }
            }
            sg_s[tid] = sg; sb_s[tid] = sb;
        }
        __syncthreads();

        // ---- tensor GEMM: 4 kb16 steps, 3-term bf16 ----
        float accD[2][8][4] = {};
        uint32_t xbase = (uint32_t)__cvta_generic_to_shared(Xh);
        int r = lane & 7, madd8 = (lane >> 3) & 1, gsel = lane >> 4;
        uint32_t abase = xbase + (warp * 32 + r + madd8 * 8) * 272 + gsel * 16;
        #pragma unroll
        for (int kb = 0; kb < 4; kb++) {
            uint32_t Ah0[4], Ah1[4], Al0[4], Al1[4];
            uint32_t ah = abase + kb * 32;
            ldsm4(Ah0, ah);
            ldsm4(Ah1, ah + 16 * 272);
            ldsm4(Al0, ah + 144);
            ldsm4(Al1, ah + 144 + 16 * 272);
            const uint4* bfk = BF + (size_t)kb * 8 * 32;
            #pragma unroll
            for (int n8 = 0; n8 < 8; n8++) {
                uint4 bv = bfk[n8 * 32 + lane];
                mma_bf16(accD[0][n8], Ah0, bv.x, bv.y);
                mma_bf16(accD[0][n8], Al0, bv.x, bv.y);
                mma_bf16(accD[0][n8], Ah0, bv.z, bv.w);
                mma_bf16(accD[1][n8], Ah1, bv.x, bv.y);
                mma_bf16(accD[1][n8], Al1, bv.x, bv.y);
                mma_bf16(accD[1][n8], Ah1, bv.z, bv.w);
            }
        }
        // ---- epilogue (LN transform) ----
        int gq = lane >> 2, oq = (lane & 3) * 2;
        #pragma unroll
        for (int tt = 0; tt < 2; tt++) {
            int pxa = warp * 32 + tt * 16 + gq;
            int pxb = pxa + 8;
            float mua = mu_s[pxa], rsa_ = rs_s[pxa];
            float mub = mu_s[pxb], rsb = rs_s[pxb];
            #pragma unroll
            for (int n8 = 0; n8 < 8; n8++) {
                #pragma unroll
                for (int q = 0; q < 2; q++) {
                    int ol = n8 * 8 + oq + q;
                    int og = o0 + ol;
                    if (og < Cout) {
                        float sg = sg_s[ol], sb = sb_s[ol];
                        float v0 = rsa_ * (accD[tt][n8][q]     - mua * sg) + sb;
                        float v1 = rsb  * (accD[tt][n8][q + 2] - mub * sg) + sb;
                        size_t obase = ((size_t)b * Cout + og) * HW + p0;
                        out[obase + pxa] = v0;
                        out[obase + pxb] = v1;
                    }
                }
            }
        }
    }
}

// =================================================================
// gated tensor-core conv (Cin=170 phys 340), bf16 3-term, 128px, occ3
// =================================================================
__global__ void __launch_bounds__(256, 3)
convgate_kernel(const float* __restrict__ in, const float* __restrict__ wt,
                float* __restrict__ out, const float* __restrict__ resid)
{
    extern __shared__ float sm[];
    float* Xh = sm;                          // 128 x 272B rows
    uint4* BF = (uint4*)(sm + 128 * XSTR);   // [4kb][8n8][32] uint4

    int b = blockIdx.z, p0 = blockIdx.x * 128;
    int tid = threadIdx.x, warp = tid >> 5, lane = tid & 31;
    int px = tid & 127, half = tid >> 7;
    int ip = p0 + px;
    const float* inb = in + (size_t)b * 340 * HW;

    float acc[8][4] = {};
    const int kbs16[3] = {4, 4, 3};
    for (int ch = 0; ch < 3; ch++) {
        if (ch) __syncthreads();
        int c0 = ch * 64;
        int nkb = kbs16[ch];
        // ---- stage X: 2 threads/px, 32 channels each ----
        char* xrow = (char*)Xh + px * 272;
        #pragma unroll
        for (int j8 = 0; j8 < 4; j8++) {
            uint16_t hb[8], lb[8];
            #pragma unroll
            for (int jj = 0; jj < 8; jj++) {
                int c = c0 + half * 32 + j8 * 8 + jj;
                float v = 0.f;
                if (c < HIDn) {
                    float a = inb[(size_t)c * HW + ip];
                    float g = inb[(size_t)(c + HIDn) * HW + ip];
                    v = gelu_f(a) * g;
                }
                bsplit(v, hb[jj], lb[jj]);
            }
            *(uint4*)(xrow + half * 64 + j8 * 16) =
                make_uint4(pk2(hb[0], hb[1]), pk2(hb[2], hb[3]), pk2(hb[4], hb[5]), pk2(hb[6], hb[7]));
            *(uint4*)(xrow + 144 + half * 64 + j8 * 16) =
                make_uint4(pk2(lb[0], lb[1]), pk2(lb[2], lb[3]), pk2(lb[4], lb[5]), pk2(lb[6], lb[7]));
        }
        // ---- stage BF ----
        int tot = nkb * 256;
        for (int e = tid; e < tot; e += 256) {
            int kb = e >> 8, rem = e & 255;
            int n8 = rem >> 5, ln2 = rem & 31;
            int g = ln2 >> 2, t2 = ln2 & 3;
            int o = n8 * 8 + g;
            int kbase = c0 + kb * 16;
            int k0 = kbase + 2 * t2, k1 = k0 + 1, k2 = kbase + 2 * t2 + 8, k3 = k2 + 1;
            float w0 = (k0 < HIDn) ? wt[(size_t)o * HIDn + k0] : 0.f;
            float w1 = (k1 < HIDn) ? wt[(size_t)o * HIDn + k1] : 0.f;
            float w2 = (k2 < HIDn) ? wt[(size_t)o * HIDn + k2] : 0.f;
            float w3 = (k3 < HIDn) ? wt[(size_t)o * HIDn + k3] : 0.f;
            uint16_t h0, l0, h1, l1, h2, l2, h3, l3;
            bsplit(w0, h0, l0); bsplit(w1, h1, l1);
            bsplit(w2, h2, l2); bsplit(w3, h3, l3);
            BF[(kb * 8 + n8) * 32 + ln2] =
                make_uint4(pk2(h0, h1), pk2(h2, h3), pk2(l0, l1), pk2(l2, l3));
        }
        __syncthreads();
        // ---- GEMM: warp = 16 px x 64 out ----
        uint32_t xbase = (uint32_t)__cvta_generic_to_shared(Xh);
        int r = lane & 7, madd8 = (lane >> 3) & 1, gsel = lane >> 4;
        uint32_t abase = xbase + (warp * 16 + r + madd8 * 8) * 272 + gsel * 16;
        #pragma unroll
        for (int kb = 0; kb < 4; kb++) {
            if (kb >= nkb) break;
            uint32_t Ah0[4], Al0[4];
            uint32_t ah = abase + kb * 32;
            ldsm4(Ah0, ah);
            ldsm4(Al0, ah + 144);
            const uint4* bfk = BF + (size_t)kb * 8 * 32;
            #pragma unroll
            for (int n8 = 0; n8 < 8; n8++) {
                uint4 bv = bfk[n8 * 32 + lane];
                mma_bf16(acc[n8], Ah0, bv.x, bv.y);
                mma_bf16(acc[n8], Al0, bv.x, bv.y);
                mma_bf16(acc[n8], Ah0, bv.z, bv.w);
            }
        }
    }
    // epilogue: + resid
    int gq = lane >> 2, oq = (lane & 3) * 2;
    int pxa = warp * 16 + gq, pxb = pxa + 8;
    #pragma unroll
    for (int n8 = 0; n8 < 8; n8++) {
        #pragma unroll
        for (int q = 0; q < 2; q++) {
            int og = n8 * 8 + oq + q;
            size_t obase = ((size_t)b * 64 + og) * HW + p0;
            out[obase + pxa] = acc[n8][q]     + resid[obase + pxa];
            out[obase + pxb] = acc[n8][q + 2] + resid[obase + pxb];
        }
    }
}

// ---------------- depthwise 3x3 conv, zero padding, 4 px/thread ----------------
__global__ void dwconv_kernel(const float* __restrict__ in, const float* __restrict__ wt,
                              float* __restrict__ out, int Ch)
{
    int c = blockIdx.y, b = blockIdx.z;
    int p = (blockIdx.x * 256 + threadIdx.x) << 2;
    int h = p >> 7, w0 = p & 127;
    const float* ib = in + ((size_t)b * Ch + c) * HW;
    const float* wc = wt + c * 9;
    float acc[4] = {0.f, 0.f, 0.f, 0.f};
    #pragma unroll
    for (int dy = -1; dy <= 1; dy++) {
        int hh = h + dy;
        if ((unsigned)hh > 127u) continue;
        const float* row = ib + (hh << 7);
        float4 mid = *(const float4*)(row + w0);
        float r0 = (w0 > 0)   ? row[w0 - 1] : 0.f;
        float r5 = (w0 < 124) ? row[w0 + 4] : 0.f;
        float r[6] = {r0, mid.x, mid.y, mid.z, mid.w, r5};
        float wa = wc[(dy + 1) * 3 + 0], wb = wc[(dy + 1) * 3 + 1], wcc = wc[(dy + 1) * 3 + 2];
        #pragma unroll
        for (int j = 0; j < 4; j++)
            acc[j] += wa * r[j] + wb * r[j + 1] + wcc * r[j + 2];
    }
    *(float4*)(out + ((size_t)b * Ch + c) * HW + p) = make_float4(acc[0], acc[1], acc[2], acc[3]);
}

// =================================================================
// RSA window attention + fused proj conv + inverse roll
// =================================================================
__global__ void __launch_bounds__(256, 3)
rsa_attn_kernel(const float* __restrict__ qkv, const float* __restrict__ pw,
                float* __restrict__ out, const float* __restrict__ temp)
{
    extern __shared__ float sm[];
    float* A   = sm;
    float* B   = sm + 64 * WSTR;
    float* C   = sm + 2 * 64 * WSTR;
    float* Pw  = sm + 3 * 64 * WSTR;
    float* inv = Pw + 64 * WSTR;
    int blk = blockIdx.x;
    int b = blk >> 8, win = blk & 255;
    int wy = win >> 4, wx = win & 15;
    int tid = threadIdx.x;
    size_t qbase = (size_t)b * 192 * HW;

    for (int e = tid; e < 4096; e += 256) {
        int p = e & 63, c = e >> 6;
        int gp = (((wy << 3) + (p >> 3)) << 7) | ((wx << 3) + (p & 7));
        A[p * WSTR + c] = qkv[qbase + c * HW + gp];
        B[p * WSTR + c] = qkv[qbase + (64 + c) * HW + gp];
        Pw[(e & 63) * WSTR + (e >> 6)] = pw[e];
    }
    __syncthreads();
    if (tid < 64) {
        int p = tid;
        float nq = 0.f, nk = 0.f;
        #pragma unroll
        for (int c = 0; c < 64; c++) {
            float a = A[p * WSTR + c]; nq += a * a;
            float bb = B[p * WSTR + c]; nk += bb * bb;
        }
        inv[p] = 1.0f / (fmaxf(sqrtf(nq), 1e-12f) * fmaxf(sqrtf(nk), 1e-12f));
    }
    __syncthreads();
    for (int e4 = tid; e4 < 1024; e4 += 256) {
        int p = e4 >> 4, c4 = e4 & 15;
        float iv = inv[p];
        float4 v = ((float4*)B)[p * (WSTR / 4) + c4];
        v.x *= iv; v.y *= iv; v.z *= iv; v.w *= iv;
        ((float4*)B)[p * (WSTR / 4) + c4] = v;
    }
    __syncthreads();
    float tscale = temp[0];
    {   // GEMM1: attn
        int c0 = (tid >> 4) << 2, d0 = (tid & 15) << 2;
        float s[4][4] = {};
        #pragma unroll 4
        for (int p = 0; p < 64; p++) {
            float4 qv = *(const float4*)(A + p * WSTR + c0);
            float4 kv = *(const float4*)(B + p * WSTR + d0);
            float qr[4] = {qv.x, qv.y, qv.z, qv.w};
            float kr[4] = {kv.x, kv.y, kv.z, kv.w};
            #pragma unroll
            for (int i = 0; i < 4; i++)
                #pragma unroll
                for (int j = 0; j < 4; j++) s[i][j] += qr[i] * kr[j];
        }
        #pragma unroll
        for (int i = 0; i < 4; i++)
            *(float4*)(C + (c0 + i) * WSTR + d0) =
                make_float4(fmaxf(0.f, tscale * s[i][0]), fmaxf(0.f, tscale * s[i][1]),
                            fmaxf(0.f, tscale * s[i][2]), fmaxf(0.f, tscale * s[i][3]));
    }
    __syncthreads();
    for (int e = tid; e < 4096; e += 256) {
        int p = e & 63, c = e >> 6;
        int gp = (((wy << 3) + (p >> 3)) << 7) | ((wx << 3) + (p & 7));
        A[c * WSTR + p] = qkv[qbase + (128 + c) * HW + gp];
    }
    __syncthreads();
    {   // GEMM2: out[d][p]
        int p0 = (tid >> 4) << 2, d0 = (tid & 15) << 2;
        float s[4][4] = {};
        #pragma unroll 4
        for (int c = 0; c < 64; c++) {
            float4 vv = *(const float4*)(A + c * WSTR + p0);
            float4 av = *(const float4*)(C + c * WSTR + d0);
            float vr[4] = {vv.x, vv.y, vv.z, vv.w};
            float ar[4] = {av.x, av.y, av.z, av.w};
            #pragma unroll
            for (int i = 0; i < 4; i++)
                #pragma unroll
                for (int j = 0; j < 4; j++) s[i][j] += vr[i] * ar[j];
        }
        #pragma unroll
        for (int j = 0; j < 4; j++)
            *(float4*)(B + (d0 + j) * WSTR + p0) = make_float4(s[0][j], s[1][j], s[2][j], s[3][j]);
    }
    __syncthreads();
    {   // GEMM3: proj
        int o0 = (tid >> 4) << 2, p0 = (tid & 15) << 2;
        float s[4][4] = {};
        #pragma unroll 4
        for (int d = 0; d < 64; d++) {
            float4 wv = *(const float4*)(Pw + d * WSTR + o0);
            float4 bv = *(const float4*)(B + d * WSTR + p0);
            float wr[4] = {wv.x, wv.y, wv.z, wv.w};
            float br[4] = {bv.x, bv.y, bv.z, bv.w};
            #pragma unroll
            for (int i = 0; i < 4; i++)
                #pragma unroll
                for (int j = 0; j < 4; j++) s[i][j] += wr[i] * br[j];
        }
        #pragma unroll
        for (int i = 0; i < 4; i++)
            *(float4*)(C + (o0 + i) * WSTR + p0) = make_float4(s[i][0], s[i][1], s[i][2], s[i][3]);
    }
    __syncthreads();
    size_t obase = (size_t)b * 64 * HW;
    for (int e = tid; e < 4096; e += 256) {
        int p = e & 63, o = e >> 6;
        int gh = (((wy << 3) + (p >> 3)) + 4) & 127;
        int gw = (((wx << 3) + (p & 7)) + 4) & 127;
        out[obase + o * HW + (gh << 7) + gw] = C[o * WSTR + p];
    }
}

// ---------------- GSA: partial Gram sums (chunked) -------------------------------
__global__ void gsa_attn_part(const float* __restrict__ qkv, float* __restrict__ part)
{
    __shared__ float red[8][80];
    int bh = blockIdx.y;
    int b = bh >> 3, hd = bh & 7;
    int chunk = blockIdx.x;
    int tid = threadIdx.x;
    const float* qb = qkv + ((size_t)b * 192 + hd * 8) * HW;
    const float* kb = qkv + ((size_t)b * 192 + 64 + hd * 8) * HW;
    float dot[8][8] = {};
    float qn[8] = {}, kn[8] = {};
    int n0 = chunk * 2048;
    for (int n = n0 + tid; n < n0 + 2048; n += 256) {
        float qv[8], kv[8];
        #pragma unroll
        for (int i = 0; i < 8; i++) { qv[i] = qb[i * HW + n]; kv[i] = kb[i * HW + n]; }
        #pragma unroll
        for (int i = 0; i < 8; i++) { qn[i] += qv[i] * qv[i]; kn[i] += kv[i] * kv[i]; }
        #pragma unroll
        for (int i = 0; i < 8; i++)
            #pragma unroll
            for (int j = 0; j < 8; j++) dot[i][j] += qv[i] * kv[j];
    }
    int lane = tid & 31, w = tid >> 5;
    #pragma unroll
    for (int i = 0; i < 8; i++)
        #pragma unroll
        for (int j = 0; j < 8; j++) {
            float v = dot[i][j];
            #pragma unroll
            for (int off = 16; off; off >>= 1) v += __shfl_xor_sync(0xffffffffu, v, off);
            if (lane == 0) red[w][i * 8 + j] = v;
        }
    #pragma unroll
    for (int i = 0; i < 8; i++) {
        float v = qn[i];
        #pragma unroll
        for (int off = 16; off; off >>= 1) v += __shfl_xor_sync(0xffffffffu, v, off);
        if (lane == 0) red[w][64 + i] = v;
        float u = kn[i];
        #pragma unroll
        for (int off = 16; off; off >>= 1) u += __shfl_xor_sync(0xffffffffu, u, off);
        if (lane == 0) red[w][72 + i] = u;
    }
    __syncthreads();
    if (tid < 80) {
        float s = 0.f;
        #pragma unroll
        for (int w2 = 0; w2 < 8; w2++) s += red[w2][tid];
        part[((size_t)bh * 8 + chunk) * 80 + tid] = s;
    }
}

__global__ void gsa_attn_final(const float* __restrict__ part, float* __restrict__ attn,
                               const float* __restrict__ temp)
{
    __shared__ float fin[80];
    int bh = blockIdx.x, tid = threadIdx.x;
    if (tid < 80) {
        float s = 0.f;
        #pragma unroll
        for (int c = 0; c < 8; c++) s += part[((size_t)bh * 8 + c) * 80 + tid];
        fin[tid] = s;
    }
    __syncthreads();
    if (tid < 64) {
        int c = tid >> 3, d = tid & 7;
        float nq = fmaxf(sqrtf(fin[64 + c]), 1e-12f);
        float nk = fmaxf(sqrtf(fin[72 + d]), 1e-12f);
        attn[(size_t)bh * 64 + tid] = fmaxf(0.f, temp[0] * fin[tid] / (nq * nk));
    }
}

// ---------------- GSA: fold proj into attention matrix -------------------------
__global__ void gsa_makeM(const float* __restrict__ attn, const float* __restrict__ pw,
                          float* __restrict__ M)
{
    __shared__ float at[512];
    int b = blockIdx.x, tid = threadIdx.x;
    for (int e = tid; e < 512; e += 256) at[e] = attn[(size_t)b * 512 + e];
    __syncthreads();
    for (int t = 0; t < 16; t++) {
        int e = t * 256 + tid;
        int o = e >> 6, chp = e & 63;
        int hd = chp >> 3, d = chp & 7;
        float s = 0.f;
        #pragma unroll
        for (int c = 0; c < 8; c++)
            s += pw[(size_t)o * 64 + c * 8 + hd] * at[hd * 64 + c * 8 + d];
        M[(size_t)b * 4096 + e] = s;
    }
}

// ---------------- GSA: out = M @ v (proj included) ------------------------------
__global__ void gsa_mv_kernel(const float* __restrict__ qkv, const float* __restrict__ M,
                              float* __restrict__ out)
{
    __shared__ float Ms[4096];
    int b = blockIdx.y, tid = threadIdx.x;
    for (int e = tid; e < 4096; e += 256) Ms[e] = M[(size_t)b * 4096 + e];
    __syncthreads();
    int n = blockIdx.x * 256 + tid;
    const float* vb = qkv + ((size_t)b * 192 + 128) * HW + n;
    float* ob = out + (size_t)b * 64 * HW + n;
    float vv[64];
    #pragma unroll
    for (int c = 0; c < 64; c++) vv[c] = vb[(size_t)c * HW];
    #pragma unroll
    for (int og = 0; og < 8; og++) {
        float acc[8] = {0.f,0.f,0.f,0.f,0.f,0.f,0.f,0.f};
        #pragma unroll
        for (int c = 0; c < 64; c++) {
            float v = vv[c];
            #pragma unroll
            for (int j = 0; j < 8; j++) acc[j] += Ms[(og * 8 + j) * 64 + c] * v;
        }
        #pragma unroll
        for (int j = 0; j < 8; j++) ob[(size_t)(og * 8 + j) * HW] = acc[j];
    }
}

// ---------------- launch ---------------------------------------------------------
extern "C" void kernel_launch(void* const* d_in, const int* in_sizes, int n_in,
                              void* d_out, int out_size)
{
    const float* x         = (const float*)d_in[0];
    const float* ln_s0_w   = (const float*)d_in[1];
    const float* ln_s0_b   = (const float*)d_in[2];
    const float* ln_s2_w   = (const float*)d_in[3];
    const float* ln_s2_b   = (const float*)d_in[4];
    const float* rsa_qkv_w = (const float*)d_in[5];
    const float* rsa_dw_w  = (const float*)d_in[6];
    const float* rsa_proj_w= (const float*)d_in[7];
    const float* rsa_temp  = (const float*)d_in[8];
    const float* ffs_in_w  = (const float*)d_in[9];
    const float* ffs_dw_w  = (const float*)d_in[10];
    const float* ffs_out_w = (const float*)d_in[11];
    const float* ln_c0_w   = (const float*)d_in[12];
    const float* ln_c0_b   = (const float*)d_in[13];
    const float* ln_c2_w   = (const float*)d_in[14];
    const float* ln_c2_b   = (const float*)d_in[15];
    const float* gsa_qkv_w = (const float*)d_in[16];
    const float* gsa_dw_w  = (const float*)d_in[17];
    const float* gsa_proj_w= (const float*)d_in[18];
    const float* gsa_temp  = (const float*)d_in[19];
    const float* ffc_in_w  = (const float*)d_in[20];
    const float* ffc_dw_w  = (const float*)d_in[21];
    const float* ffc_out_w = (const float*)d_in[22];
    float* outp = (float*)d_out;

    float *bufR, *bufX, *bufG, *big1, *big2, *attnb, *partb, *Mb;
    cudaGetSymbolAddress((void**)&bufR,  g_bufR);
    cudaGetSymbolAddress((void**)&bufX,  g_bufX);
    cudaGetSymbolAddress((void**)&bufG,  g_bufG);
    cudaGetSymbolAddress((void**)&big1,  g_big1);
    cudaGetSymbolAddress((void**)&big2,  g_big2);
    cudaGetSymbolAddress((void**)&attnb, g_attn);
    cudaGetSymbolAddress((void**)&partb, g_part);
    cudaGetSymbolAddress((void**)&Mb,    g_M);

    const int ctc_smem = (256 * XSTR + 4096 + 256 + 256 + 64 + 64) * (int)sizeof(float); // 88576
    const int cg_smem  = (128 * XSTR + 4096) * (int)sizeof(float);                       // 51200
    const int rsa_smem = (4 * 64 * WSTR + 64) * (int)sizeof(float);
    cudaFuncSetAttribute(convtc_kernel, cudaFuncAttributeMaxDynamicSharedMemorySize, ctc_smem);
    cudaFuncSetAttribute(convgate_kernel, cudaFuncAttributeMaxDynamicSharedMemorySize, cg_smem);
    cudaFuncSetAttribute(rsa_attn_kernel, cudaFuncAttributeMaxDynamicSharedMemorySize, rsa_smem);

    // ---- stage 1: RSA + spatial FFN ----
    convtc_kernel<<<dim3(64, 1, Bn), 256, ctc_smem>>>(x, nullptr, ln_s0_w, ln_s0_b, rsa_qkv_w, big1, 192, 4);
    dwconv_kernel<<<dim3(16, 192, Bn), 256>>>(big1, rsa_dw_w, big2, 192);
    rsa_attn_kernel<<<Bn * 256, 256, rsa_smem>>>(big2, rsa_proj_w, bufR, rsa_temp);
    convtc_kernel<<<dim3(64, 1, Bn), 256, ctc_smem>>>(bufR, x, ln_s2_w, ln_s2_b, ffs_in_w, big1, 340, 0);
    dwconv_kernel<<<dim3(16, 340, Bn), 256>>>(big1, ffs_dw_w, big2, 340);
    convgate_kernel<<<dim3(128, 1, Bn), 256, cg_smem>>>(big2, ffs_out_w, bufX, bufR);

    // ---- stage 2: GSA + channel FFN ----
    convtc_kernel<<<dim3(64, 1, Bn), 256, ctc_smem>>>(bufX, nullptr, ln_c0_w, ln_c0_b, gsa_qkv_w, big1, 192, 0);
    dwconv_kernel<<<dim3(16, 192, Bn), 256>>>(big1, gsa_dw_w, big2, 192);
    gsa_attn_part<<<dim3(8, 64), 256>>>(big2, partb);
    gsa_attn_final<<<64, 128>>>(partb, attnb, gsa_temp);
    gsa_makeM<<<Bn, 256>>>(attnb, gsa_proj_w, Mb);
    gsa_mv_kernel<<<dim3(64, Bn), 256>>>(big2, Mb, bufG);
    convtc_kernel<<<dim3(64, 1, Bn), 256, ctc_smem>>>(bufG, bufX, ln_c2_w, ln_c2_b, ffc_in_w, big1, 340, 0);
    dwconv_kernel<<<dim3(16, 340, Bn), 256>>>(big1, ffc_dw_w, big2, 340);
    convgate_kernel<<<dim3(128, 1, Bn), 256, cg_smem>>>(big2, ffc_out_w, outp, bufG);
}

// round 8
// speedup vs baseline: 1.8197x; 1.0571x over previous
#include <cuda_runtime.h>
#include <math.h>
#include <stdint.h>

#define HW    16384
#define Bn    8
#define HIDn  170
#define ROWB  144     // bytes per staged X row: 64 fp16 (128B) + 16B pad -> conflict-free
#define XROWF 36      // floats per row
#define WSTR  68

// ---------------- scratch (static device memory) ----------------
__device__ float g_bufR[Bn * 64 * HW];
__device__ float g_bufX[Bn * 64 * HW];
__device__ float g_bufG[Bn * 64 * HW];
__device__ float g_big1[Bn * 340 * HW];
__device__ float g_big2[Bn * 340 * HW];
__device__ float g_attn[Bn * 8 * 64];
__device__ float g_part[64 * 8 * 80];
__device__ float g_M[Bn * 64 * 64];

__device__ __forceinline__ float gelu_f(float x) {
    return 0.5f * x * (1.0f + erff(x * 0.70710678118654752f));
}
__device__ __forceinline__ uint16_t f16b(float x) {
    uint16_t r; asm("cvt.rn.f16.f32 %0, %1;" : "=h"(r) : "f"(x)); return r;
}
__device__ __forceinline__ uint32_t pk2(uint16_t lo, uint16_t hi) {
    return (uint32_t)lo | ((uint32_t)hi << 16);
}
__device__ __forceinline__ void ldsm4(uint32_t* a, uint32_t addr) {
    asm volatile("ldmatrix.sync.aligned.m8n8.x4.shared.b16 {%0,%1,%2,%3}, [%4];"
        : "=r"(a[0]), "=r"(a[1]), "=r"(a[2]), "=r"(a[3]) : "r"(addr));
}
__device__ __forceinline__ void mma_f16(float* d, const uint32_t* a, uint32_t b0, uint32_t b1) {
    asm volatile("mma.sync.aligned.m16n8k16.row.col.f32.f16.f16.f32 "
        "{%0,%1,%2,%3}, {%4,%5,%6,%7}, {%8,%9}, {%0,%1,%2,%3};"
        : "+f"(d[0]), "+f"(d[1]), "+f"(d[2]), "+f"(d[3])
        : "r"(a[0]), "r"(a[1]), "r"(a[2]), "r"(a[3]), "r"(b0), "r"(b1));
}

// =================================================================
// LN-fused tensor-core conv1x1 (Cin=64), single-term fp16.
// X row (144B): 64 fp16 ch at [0,128). Stages X ONCE, loops
// out-tiles of 64 (Cout up to 384). 256px x 64out, 8 warps.
// =================================================================
__global__ void __launch_bounds__(256, 2)
convtc_kernel(const float* __restrict__ in, const float* __restrict__ addp,
              const float* __restrict__ lnw, const float* __restrict__ lnb,
              const float* __restrict__ wt, float* __restrict__ out,
              int Cout, int shift)
{
    extern __shared__ float sm[];
    float* Xh   = sm;                          // 256 rows x 144B = 9216 floats
    uint2* BF   = (uint2*)(sm + 256 * XROWF);  // [4kb][8n8][32] uint2 = 8KB
    float* mu_s = sm + 256 * XROWF + 2048;     // [256]
    float* rs_s = mu_s + 256;                  // [256]
    float* sg_s = rs_s + 256;                  // [64]
    float* sb_s = sg_s + 64;                   // [64]

    int b = blockIdx.z, p0 = blockIdx.x * 256;
    int tid = threadIdx.x, warp = tid >> 5, lane = tid & 31;
    const float* inb = in + (size_t)b * 64 * HW;
    const float* adb = addp ? addp + (size_t)b * 64 * HW : nullptr;

    int p = p0 + tid, ip = p;
    if (shift) {
        int hh = ((p >> 7) + shift) & 127, ww = ((p & 127) + shift) & 127;
        ip = (hh << 7) | ww;
    }
    // ---- stage X once (fp16) + LN stats ----
    float s_sum = 0.f, s_sq = 0.f;
    char* xrow = (char*)Xh + tid * ROWB;
    #pragma unroll
    for (int j8 = 0; j8 < 8; j8++) {
        uint16_t hb[8];
        #pragma unroll
        for (int jj = 0; jj < 8; jj++) {
            int c = j8 * 8 + jj;
            float v = inb[(size_t)c * HW + ip];
            if (adb) v += adb[(size_t)c * HW + ip];
            s_sum += v; s_sq += v * v;
            hb[jj] = f16b(v);
        }
        *(uint4*)(xrow + j8 * 16) =
            make_uint4(pk2(hb[0], hb[1]), pk2(hb[2], hb[3]), pk2(hb[4], hb[5]), pk2(hb[6], hb[7]));
    }
    {
        float m = s_sum * 0.015625f;
        float var = s_sq * 0.015625f - m * m;
        mu_s[tid] = m;
        rs_s[tid] = rsqrtf(fmaxf(var, 0.f) + 1e-5f);
    }

    int ntile = (Cout + 63) >> 6;
    for (int t = 0; t < ntile; t++) {
        __syncthreads();
        int o0 = t << 6;
        // ---- stage W fragments (fp16, gamma folded) ----
        #pragma unroll
        for (int i = 0; i < 4; i++) {
            int e = i * 256 + tid;
            int kb = e >> 8, rem = e & 255;
            int n8 = rem >> 5, ln2 = rem & 31;
            int g = ln2 >> 2, t2 = ln2 & 3;
            int og = o0 + n8 * 8 + g;
            int kbase = kb * 16;
            float w0 = 0.f, w1 = 0.f, w2 = 0.f, w3 = 0.f;
            if (og < Cout) {
                const float* wr = wt + (size_t)og * 64 + kbase;
                w0 = wr[2 * t2]     * lnw[kbase + 2 * t2];
                w1 = wr[2 * t2 + 1] * lnw[kbase + 2 * t2 + 1];
                w2 = wr[2 * t2 + 8] * lnw[kbase + 2 * t2 + 8];
                w3 = wr[2 * t2 + 9] * lnw[kbase + 2 * t2 + 9];
            }
            BF[(kb * 8 + n8) * 32 + ln2] =
                make_uint2(pk2(f16b(w0), f16b(w1)), pk2(f16b(w2), f16b(w3)));
        }
        if (tid < 64) {
            float sg = 0.f, sb = 0.f;
            int og = o0 + tid;
            if (og < Cout) {
                const float* wr = wt + (size_t)og * 64;
                #pragma unroll 8
                for (int k = 0; k < 64; k++) { sg += wr[k] * lnw[k]; sb += wr[k] * lnb[k]; }
            }
            sg_s[tid] = sg; sb_s[tid] = sb;
        }
        __syncthreads();

        // ---- tensor GEMM: 4 kb16 steps, single fp16 term ----
        float accD[2][8][4] = {};
        uint32_t xbase = (uint32_t)__cvta_generic_to_shared(Xh);
        int r = lane & 7, madd8 = (lane >> 3) & 1, gsel = lane >> 4;
        uint32_t abase = xbase + (warp * 32 + r + madd8 * 8) * ROWB + gsel * 16;
        #pragma unroll
        for (int kb = 0; kb < 4; kb++) {
            uint32_t A0[4], A1[4];
            uint32_t ah = abase + kb * 32;
            ldsm4(A0, ah);
            ldsm4(A1, ah + 16 * ROWB);
            const uint2* bfk = BF + (size_t)kb * 8 * 32;
            #pragma unroll
            for (int n8 = 0; n8 < 8; n8++) {
                uint2 bv = bfk[n8 * 32 + lane];
                mma_f16(accD[0][n8], A0, bv.x, bv.y);
                mma_f16(accD[1][n8], A1, bv.x, bv.y);
            }
        }
        // ---- epilogue (LN transform) ----
        int gq = lane >> 2, oq = (lane & 3) * 2;
        #pragma unroll
        for (int tt = 0; tt < 2; tt++) {
            int pxa = warp * 32 + tt * 16 + gq;
            int pxb = pxa + 8;
            float mua = mu_s[pxa], rsa_ = rs_s[pxa];
            float mub = mu_s[pxb], rsb = rs_s[pxb];
            #pragma unroll
            for (int n8 = 0; n8 < 8; n8++) {
                #pragma unroll
                for (int q = 0; q < 2; q++) {
                    int ol = n8 * 8 + oq + q;
                    int og = o0 + ol;
                    if (og < Cout) {
                        float sg = sg_s[ol], sb = sb_s[ol];
                        float v0 = rsa_ * (accD[tt][n8][q]     - mua * sg) + sb;
                        float v1 = rsb  * (accD[tt][n8][q + 2] - mub * sg) + sb;
                        size_t obase = ((size_t)b * Cout + og) * HW + p0;
                        out[obase + pxa] = v0;
                        out[obase + pxb] = v1;
                    }
                }
            }
        }
    }
}

// =================================================================
// gated tensor-core conv (Cin=170 phys 340), single fp16, 128px, occ3
// =================================================================
__global__ void __launch_bounds__(256, 3)
convgate_kernel(const float* __restrict__ in, const float* __restrict__ wt,
                float* __restrict__ out, const float* __restrict__ resid)
{
    extern __shared__ float sm[];
    float* Xh = sm;                           // 128 rows x 144B = 4608 floats
    uint2* BF = (uint2*)(sm + 128 * XROWF);   // [4kb][8n8][32] uint2

    int b = blockIdx.z, p0 = blockIdx.x * 128;
    int tid = threadIdx.x, warp = tid >> 5, lane = tid & 31;
    int px = tid & 127, half = tid >> 7;
    int ip = p0 + px;
    const float* inb = in + (size_t)b * 340 * HW;

    float acc[8][4] = {};
    const int kbs16[3] = {4, 4, 3};
    for (int ch = 0; ch < 3; ch++) {
        if (ch) __syncthreads();
        int c0 = ch * 64;
        int nkb = kbs16[ch];
        // ---- stage X: 2 threads/px, 32 channels each ----
        char* xrow = (char*)Xh + px * ROWB;
        #pragma unroll
        for (int j8 = 0; j8 < 4; j8++) {
            uint16_t hb[8];
            #pragma unroll
            for (int jj = 0; jj < 8; jj++) {
                int c = c0 + half * 32 + j8 * 8 + jj;
                float v = 0.f;
                if (c < HIDn) {
                    float a = inb[(size_t)c * HW + ip];
                    float g = inb[(size_t)(c + HIDn) * HW + ip];
                    v = gelu_f(a) * g;
                }
                hb[jj] = f16b(v);
            }
            *(uint4*)(xrow + half * 64 + j8 * 16) =
                make_uint4(pk2(hb[0], hb[1]), pk2(hb[2], hb[3]), pk2(hb[4], hb[5]), pk2(hb[6], hb[7]));
        }
        // ---- stage BF ----
        int tot = nkb * 256;
        for (int e = tid; e < tot; e += 256) {
            int kb = e >> 8, rem = e & 255;
            int n8 = rem >> 5, ln2 = rem & 31;
            int g = ln2 >> 2, t2 = ln2 & 3;
            int o = n8 * 8 + g;
            int kbase = c0 + kb * 16;
            int k0 = kbase + 2 * t2, k1 = k0 + 1, k2 = kbase + 2 * t2 + 8, k3 = k2 + 1;
            float w0 = (k0 < HIDn) ? wt[(size_t)o * HIDn + k0] : 0.f;
            float w1 = (k1 < HIDn) ? wt[(size_t)o * HIDn + k1] : 0.f;
            float w2 = (k2 < HIDn) ? wt[(size_t)o * HIDn + k2] : 0.f;
            float w3 = (k3 < HIDn) ? wt[(size_t)o * HIDn + k3] : 0.f;
            BF[(kb * 8 + n8) * 32 + ln2] =
                make_uint2(pk2(f16b(w0), f16b(w1)), pk2(f16b(w2), f16b(w3)));
        }
        __syncthreads();
        // ---- GEMM: warp = 16 px x 64 out ----
        uint32_t xbase = (uint32_t)__cvta_generic_to_shared(Xh);
        int r = lane & 7, madd8 = (lane >> 3) & 1, gsel = lane >> 4;
        uint32_t abase = xbase + (warp * 16 + r + madd8 * 8) * ROWB + gsel * 16;
        #pragma unroll
        for (int kb = 0; kb < 4; kb++) {
            if (kb >= nkb) break;
            uint32_t A0[4];
            ldsm4(A0, abase + kb * 32);
            const uint2* bfk = BF + (size_t)kb * 8 * 32;
            #pragma unroll
            for (int n8 = 0; n8 < 8; n8++) {
                uint2 bv = bfk[n8 * 32 + lane];
                mma_f16(acc[n8], A0, bv.x, bv.y);
            }
        }
    }
    // epilogue: + resid
    int gq = lane >> 2, oq = (lane & 3) * 2;
    int pxa = warp * 16 + gq, pxb = pxa + 8;
    #pragma unroll
    for (int n8 = 0; n8 < 8; n8++) {
        #pragma unroll
        for (int q = 0; q < 2; q++) {
            int og = n8 * 8 + oq + q;
            size_t obase = ((size_t)b * 64 + og) * HW + p0;
            out[obase + pxa] = acc[n8][q]     + resid[obase + pxa];
            out[obase + pxb] = acc[n8][q + 2] + resid[obase + pxb];
        }
    }
}

// ---------------- depthwise 3x3 conv, zero padding, 4 px/thread ----------------
__global__ void dwconv_kernel(const float* __restrict__ in, const float* __restrict__ wt,
                              float* __restrict__ out, int Ch)
{
    int c = blockIdx.y, b = blockIdx.z;
    int p = (blockIdx.x * 256 + threadIdx.x) << 2;
    int h = p >> 7, w0 = p & 127;
    const float* ib = in + ((size_t)b * Ch + c) * HW;
    const float* wc = wt + c * 9;
    float acc[4] = {0.f, 0.f, 0.f, 0.f};
    #pragma unroll
    for (int dy = -1; dy <= 1; dy++) {
        int hh = h + dy;
        if ((unsigned)hh > 127u) continue;
        const float* row = ib + (hh << 7);
        float4 mid = *(const float4*)(row + w0);
        float r0 = (w0 > 0)   ? row[w0 - 1] : 0.f;
        float r5 = (w0 < 124) ? row[w0 + 4] : 0.f;
        float r[6] = {r0, mid.x, mid.y, mid.z, mid.w, r5};
        float wa = wc[(dy + 1) * 3 + 0], wb = wc[(dy + 1) * 3 + 1], wcc = wc[(dy + 1) * 3 + 2];
        #pragma unroll
        for (int j = 0; j < 4; j++)
            acc[j] += wa * r[j] + wb * r[j + 1] + wcc * r[j + 2];
    }
    *(float4*)(out + ((size_t)b * Ch + c) * HW + p) = make_float4(acc[0], acc[1], acc[2], acc[3]);
}

// =================================================================
// RSA window attention + fused proj conv + inverse roll
// =================================================================
__global__ void __launch_bounds__(256, 3)
rsa_attn_kernel(const float* __restrict__ qkv, const float* __restrict__ pw,
                float* __restrict__ out, const float* __restrict__ temp)
{
    extern __shared__ float sm[];
    float* A   = sm;
    float* B   = sm + 64 * WSTR;
    float* C   = sm + 2 * 64 * WSTR;
    float* Pw  = sm + 3 * 64 * WSTR;
    float* inv = Pw + 64 * WSTR;
    int blk = blockIdx.x;
    int b = blk >> 8, win = blk & 255;
    int wy = win >> 4, wx = win & 15;
    int tid = threadIdx.x;
    size_t qbase = (size_t)b * 192 * HW;

    for (int e = tid; e < 4096; e += 256) {
        int p = e & 63, c = e >> 6;
        int gp = (((wy << 3) + (p >> 3)) << 7) | ((wx << 3) + (p & 7));
        A[p * WSTR + c] = qkv[qbase + c * HW + gp];
        B[p * WSTR + c] = qkv[qbase + (64 + c) * HW + gp];
        Pw[(e & 63) * WSTR + (e >> 6)] = pw[e];
    }
    __syncthreads();
    if (tid < 64) {
        int p = tid;
        float nq = 0.f, nk = 0.f;
        #pragma unroll
        for (int c = 0; c < 64; c++) {
            float a = A[p * WSTR + c]; nq += a * a;
            float bb = B[p * WSTR + c]; nk += bb * bb;
        }
        inv[p] = 1.0f / (fmaxf(sqrtf(nq), 1e-12f) * fmaxf(sqrtf(nk), 1e-12f));
    }
    __syncthreads();
    for (int e4 = tid; e4 < 1024; e4 += 256) {
        int p = e4 >> 4, c4 = e4 & 15;
        float iv = inv[p];
        float4 v = ((float4*)B)[p * (WSTR / 4) + c4];
        v.x *= iv; v.y *= iv; v.z *= iv; v.w *= iv;
        ((float4*)B)[p * (WSTR / 4) + c4] = v;
    }
    __syncthreads();
    float tscale = temp[0];
    {   // GEMM1: attn
        int c0 = (tid >> 4) << 2, d0 = (tid & 15) << 2;
        float s[4][4] = {};
        #pragma unroll 4
        for (int p = 0; p < 64; p++) {
            float4 qv = *(const float4*)(A + p * WSTR + c0);
            float4 kv = *(const float4*)(B + p * WSTR + d0);
            float qr[4] = {qv.x, qv.y, qv.z, qv.w};
            float kr[4] = {kv.x, kv.y, kv.z, kv.w};
            #pragma unroll
            for (int i = 0; i < 4; i++)
                #pragma unroll
                for (int j = 0; j < 4; j++) s[i][j] += qr[i] * kr[j];
        }
        #pragma unroll
        for (int i = 0; i < 4; i++)
            *(float4*)(C + (c0 + i) * WSTR + d0) =
                make_float4(fmaxf(0.f, tscale * s[i][0]), fmaxf(0.f, tscale * s[i][1]),
                            fmaxf(0.f, tscale * s[i][2]), fmaxf(0.f, tscale * s[i][3]));
    }
    __syncthreads();
    for (int e = tid; e < 4096; e += 256) {
        int p = e & 63, c = e >> 6;
        int gp = (((wy << 3) + (p >> 3)) << 7) | ((wx << 3) + (p & 7));
        A[c * WSTR + p] = qkv[qbase + (128 + c) * HW + gp];
    }
    __syncthreads();
    {   // GEMM2: out[d][p]
        int p0 = (tid >> 4) << 2, d0 = (tid & 15) << 2;
        float s[4][4] = {};
        #pragma unroll 4
        for (int c = 0; c < 64; c++) {
            float4 vv = *(const float4*)(A + c * WSTR + p0);
            float4 av = *(const float4*)(C + c * WSTR + d0);
            float vr[4] = {vv.x, vv.y, vv.z, vv.w};
            float ar[4] = {av.x, av.y, av.z, av.w};
            #pragma unroll
            for (int i = 0; i < 4; i++)
                #pragma unroll
                for (int j = 0; j < 4; j++) s[i][j] += vr[i] * ar[j];
        }
        #pragma unroll
        for (int j = 0; j < 4; j++)
            *(float4*)(B + (d0 + j) * WSTR + p0) = make_float4(s[0][j], s[1][j], s[2][j], s[3][j]);
    }
    __syncthreads();
    {   // GEMM3: proj
        int o0 = (tid >> 4) << 2, p0 = (tid & 15) << 2;
        float s[4][4] = {};
        #pragma unroll 4
        for (int d = 0; d < 64; d++) {
            float4 wv = *(const float4*)(Pw + d * WSTR + o0);
            float4 bv = *(const float4*)(B + d * WSTR + p0);
            float wr[4] = {wv.x, wv.y, wv.z, wv.w};
            float br[4] = {bv.x, bv.y, bv.z, bv.w};
            #pragma unroll
            for (int i = 0; i < 4; i++)
                #pragma unroll
                for (int j = 0; j < 4; j++) s[i][j] += wr[i] * br[j];
        }
        #pragma unroll
        for (int i = 0; i < 4; i++)
            *(float4*)(C + (o0 + i) * WSTR + p0) = make_float4(s[i][0], s[i][1], s[i][2], s[i][3]);
    }
    __syncthreads();
    size_t obase = (size_t)b * 64 * HW;
    for (int e = tid; e < 4096; e += 256) {
        int p = e & 63, o = e >> 6;
        int gh = (((wy << 3) + (p >> 3)) + 4) & 127;
        int gw = (((wx << 3) + (p & 7)) + 4) & 127;
        out[obase + o * HW + (gh << 7) + gw] = C[o * WSTR + p];
    }
}

// ---------------- GSA: partial Gram sums (chunked) -------------------------------
__global__ void gsa_attn_part(const float* __restrict__ qkv, float* __restrict__ part)
{
    __shared__ float red[8][80];
    int bh = blockIdx.y;
    int b = bh >> 3, hd = bh & 7;
    int chunk = blockIdx.x;
    int tid = threadIdx.x;
    const float* qb = qkv + ((size_t)b * 192 + hd * 8) * HW;
    const float* kb = qkv + ((size_t)b * 192 + 64 + hd * 8) * HW;
    float dot[8][8] = {};
    float qn[8] = {}, kn[8] = {};
    int n0 = chunk * 2048;
    for (int n = n0 + tid; n < n0 + 2048; n += 256) {
        float qv[8], kv[8];
        #pragma unroll
        for (int i = 0; i < 8; i++) { qv[i] = qb[i * HW + n]; kv[i] = kb[i * HW + n]; }
        #pragma unroll
        for (int i = 0; i < 8; i++) { qn[i] += qv[i] * qv[i]; kn[i] += kv[i] * kv[i]; }
        #pragma unroll
        for (int i = 0; i < 8; i++)
            #pragma unroll
            for (int j = 0; j < 8; j++) dot[i][j] += qv[i] * kv[j];
    }
    int lane = tid & 31, w = tid >> 5;
    #pragma unroll
    for (int i = 0; i < 8; i++)
        #pragma unroll
        for (int j = 0; j < 8; j++) {
            float v = dot[i][j];
            #pragma unroll
            for (int off = 16; off; off >>= 1) v += __shfl_xor_sync(0xffffffffu, v, off);
            if (lane == 0) red[w][i * 8 + j] = v;
        }
    #pragma unroll
    for (int i = 0; i < 8; i++) {
        float v = qn[i];
        #pragma unroll
        for (int off = 16; off; off >>= 1) v += __shfl_xor_sync(0xffffffffu, v, off);
        if (lane == 0) red[w][64 + i] = v;
        float u = kn[i];
        #pragma unroll
        for (int off = 16; off; off >>= 1) u += __shfl_xor_sync(0xffffffffu, u, off);
        if (lane == 0) red[w][72 + i] = u;
    }
    __syncthreads();
    if (tid < 80) {
        float s = 0.f;
        #pragma unroll
        for (int w2 = 0; w2 < 8; w2++) s += red[w2][tid];
        part[((size_t)bh * 8 + chunk) * 80 + tid] = s;
    }
}

__global__ void gsa_attn_final(const float* __restrict__ part, float* __restrict__ attn,
                               const float* __restrict__ temp)
{
    __shared__ float fin[80];
    int bh = blockIdx.x, tid = threadIdx.x;
    if (tid < 80) {
        float s = 0.f;
        #pragma unroll
        for (int c = 0; c < 8; c++) s += part[((size_t)bh * 8 + c) * 80 + tid];
        fin[tid] = s;
    }
    __syncthreads();
    if (tid < 64) {
        int c = tid >> 3, d = tid & 7;
        float nq = fmaxf(sqrtf(fin[64 + c]), 1e-12f);
        float nk = fmaxf(sqrtf(fin[72 + d]), 1e-12f);
        attn[(size_t)bh * 64 + tid] = fmaxf(0.f, temp[0] * fin[tid] / (nq * nk));
    }
}

// ---------------- GSA: fold proj into attention matrix -------------------------
__global__ void gsa_makeM(const float* __restrict__ attn, const float* __restrict__ pw,
                          float* __restrict__ M)
{
    __shared__ float at[512];
    int b = blockIdx.x, tid = threadIdx.x;
    for (int e = tid; e < 512; e += 256) at[e] = attn[(size_t)b * 512 + e];
    __syncthreads();
    for (int t = 0; t < 16; t++) {
        int e = t * 256 + tid;
        int o = e >> 6, chp = e & 63;
        int hd = chp >> 3, d = chp & 7;
        float s = 0.f;
        #pragma unroll
        for (int c = 0; c < 8; c++)
            s += pw[(size_t)o * 64 + c * 8 + hd] * at[hd * 64 + c * 8 + d];
        M[(size_t)b * 4096 + e] = s;
    }
}

// ---------------- GSA: out = M @ v (proj included) ------------------------------
__global__ void gsa_mv_kernel(const float* __restrict__ qkv, const float* __restrict__ M,
                              float* __restrict__ out)
{
    __shared__ float Ms[4096];
    int b = blockIdx.y, tid = threadIdx.x;
    for (int e = tid; e < 4096; e += 256) Ms[e] = M[(size_t)b * 4096 + e];
    __syncthreads();
    int n = blockIdx.x * 256 + tid;
    const float* vb = qkv + ((size_t)b * 192 + 128) * HW + n;
    float* ob = out + (size_t)b * 64 * HW + n;
    float vv[64];
    #pragma unroll
    for (int c = 0; c < 64; c++) vv[c] = vb[(size_t)c * HW];
    #pragma unroll
    for (int og = 0; og < 8; og++) {
        float acc[8] = {0.f,0.f,0.f,0.f,0.f,0.f,0.f,0.f};
        #pragma unroll
        for (int c = 0; c < 64; c++) {
            float v = vv[c];
            #pragma unroll
            for (int j = 0; j < 8; j++) acc[j] += Ms[(og * 8 + j) * 64 + c] * v;
        }
        #pragma unroll
        for (int j = 0; j < 8; j++) ob[(size_t)(og * 8 + j) * HW] = acc[j];
    }
}

// ---------------- launch ---------------------------------------------------------
extern "C" void kernel_launch(void* const* d_in, const int* in_sizes, int n_in,
                              void* d_out, int out_size)
{
    const float* x         = (const float*)d_in[0];
    const float* ln_s0_w   = (const float*)d_in[1];
    const float* ln_s0_b   = (const float*)d_in[2];
    const float* ln_s2_w   = (const float*)d_in[3];
    const float* ln_s2_b   = (const float*)d_in[4];
    const float* rsa_qkv_w = (const float*)d_in[5];
    const float* rsa_dw_w  = (const float*)d_in[6];
    const float* rsa_proj_w= (const float*)d_in[7];
    const float* rsa_temp  = (const float*)d_in[8];
    const float* ffs_in_w  = (const float*)d_in[9];
    const float* ffs_dw_w  = (const float*)d_in[10];
    const float* ffs_out_w = (const float*)d_in[11];
    const float* ln_c0_w   = (const float*)d_in[12];
    const float* ln_c0_b   = (const float*)d_in[13];
    const float* ln_c2_w   = (const float*)d_in[14];
    const float* ln_c2_b   = (const float*)d_in[15];
    const float* gsa_qkv_w = (const float*)d_in[16];
    const float* gsa_dw_w  = (const float*)d_in[17];
    const float* gsa_proj_w= (const float*)d_in[18];
    const float* gsa_temp  = (const float*)d_in[19];
    const float* ffc_in_w  = (const float*)d_in[20];
    const float* ffc_dw_w  = (const float*)d_in[21];
    const float* ffc_out_w = (const float*)d_in[22];
    float* outp = (float*)d_out;

    float *bufR, *bufX, *bufG, *big1, *big2, *attnb, *partb, *Mb;
    cudaGetSymbolAddress((void**)&bufR,  g_bufR);
    cudaGetSymbolAddress((void**)&bufX,  g_bufX);
    cudaGetSymbolAddress((void**)&bufG,  g_bufG);
    cudaGetSymbolAddress((void**)&big1,  g_big1);
    cudaGetSymbolAddress((void**)&big2,  g_big2);
    cudaGetSymbolAddress((void**)&attnb, g_attn);
    cudaGetSymbolAddress((void**)&partb, g_part);
    cudaGetSymbolAddress((void**)&Mb,    g_M);

    const int ctc_smem = (256 * XROWF + 2048 + 256 + 256 + 64 + 64) * (int)sizeof(float); // 47616
    const int cg_smem  = (128 * XROWF + 2048) * (int)sizeof(float);                       // 26624
    const int rsa_smem = (4 * 64 * WSTR + 64) * (int)sizeof(float);
    cudaFuncSetAttribute(convtc_kernel, cudaFuncAttributeMaxDynamicSharedMemorySize, ctc_smem);
    cudaFuncSetAttribute(convgate_kernel, cudaFuncAttributeMaxDynamicSharedMemorySize, cg_smem);
    cudaFuncSetAttribute(rsa_attn_kernel, cudaFuncAttributeMaxDynamicSharedMemorySize, rsa_smem);

    // ---- stage 1: RSA + spatial FFN ----
    convtc_kernel<<<dim3(64, 1, Bn), 256, ctc_smem>>>(x, nullptr, ln_s0_w, ln_s0_b, rsa_qkv_w, big1, 192, 4);
    dwconv_kernel<<<dim3(16, 192, Bn), 256>>>(big1, rsa_dw_w, big2, 192);
    rsa_attn_kernel<<<Bn * 256, 256, rsa_smem>>>(big2, rsa_proj_w, bufR, rsa_temp);
    convtc_kernel<<<dim3(64, 1, Bn), 256, ctc_smem>>>(bufR, x, ln_s2_w, ln_s2_b, ffs_in_w, big1, 340, 0);
    dwconv_kernel<<<dim3(16, 340, Bn), 256>>>(big1, ffs_dw_w, big2, 340);
    convgate_kernel<<<dim3(128, 1, Bn), 256, cg_smem>>>(big2, ffs_out_w, bufX, bufR);

    // ---- stage 2: GSA + channel FFN ----
    convtc_kernel<<<dim3(64, 1, Bn), 256, ctc_smem>>>(bufX, nullptr, ln_c0_w, ln_c0_b, gsa_qkv_w, big1, 192, 0);
    dwconv_kernel<<<dim3(16, 192, Bn), 256>>>(big1, gsa_dw_w, big2, 192);
    gsa_attn_part<<<dim3(8, 64), 256>>>(big2, partb);
    gsa_attn_final<<<64, 128>>>(partb, attnb, gsa_temp);
    gsa_makeM<<<Bn, 256>>>(attnb, gsa_proj_w, Mb);
    gsa_mv_kernel<<<dim3(64, Bn), 256>>>(big2, Mb, bufG);
    convtc_kernel<<<dim3(64, 1, Bn), 256, ctc_smem>>>(bufG, bufX, ln_c2_w, ln_c2_b, ffc_in_w, big1, 340, 0);
    dwconv_kernel<<<dim3(16, 340, Bn), 256>>>(big1, ffc_dw_w, big2, 340);
    convgate_kernel<<<dim3(128, 1, Bn), 256, cg_smem>>>(big2, ffc_out_w, outp, bufG);
}

// round 9
// speedup vs baseline: 1.8725x; 1.0290x over previous
#include <cuda_runtime.h>
#include <cuda_fp16.h>
#include <math.h>
#include <stdint.h>

#define HW    16384
#define Bn    8
#define HIDn  170
#define XSTR  68      // floats per X row = 272B = 17 x 16B granules (conflict-free)
#define WSTR  68

// ---------------- scratch (static device memory) ----------------
__device__ float  g_bufR[Bn * 64 * HW];
__device__ float  g_bufX[Bn * 64 * HW];
__device__ float  g_bufG[Bn * 64 * HW];
__device__ __half g_big1[Bn * 340 * HW];
__device__ __half g_big2[Bn * 340 * HW];
__device__ float  g_attn[Bn * 8 * 64];
__device__ float  g_part[64 * 8 * 80];
__device__ float  g_M[Bn * 64 * 64];

__device__ __forceinline__ float gelu_f(float x) {
    return 0.5f * x * (1.0f + erff(x * 0.70710678118654752f));
}
__device__ __forceinline__ uint16_t bf16b(float x) {
    uint16_t r; asm("cvt.rn.bf16.f32 %0, %1;" : "=h"(r) : "f"(x)); return r;
}
__device__ __forceinline__ uint32_t pk2(uint16_t lo, uint16_t hi) {
    return (uint32_t)lo | ((uint32_t)hi << 16);
}
__device__ __forceinline__ void bsplit(float v, uint16_t& h, uint16_t& l) {
    h = bf16b(v);
    float hf = __uint_as_float((uint32_t)h << 16);
    l = bf16b(v - hf);
}
__device__ __forceinline__ void ldsm4(uint32_t* a, uint32_t addr) {
    asm volatile("ldmatrix.sync.aligned.m8n8.x4.shared.b16 {%0,%1,%2,%3}, [%4];"
        : "=r"(a[0]), "=r"(a[1]), "=r"(a[2]), "=r"(a[3]) : "r"(addr));
}
__device__ __forceinline__ void mma_bf16(float* d, const uint32_t* a, uint32_t b0, uint32_t b1) {
    asm volatile("mma.sync.aligned.m16n8k16.row.col.f32.bf16.bf16.f32 "
        "{%0,%1,%2,%3}, {%4,%5,%6,%7}, {%8,%9}, {%0,%1,%2,%3};"
        : "+f"(d[0]), "+f"(d[1]), "+f"(d[2]), "+f"(d[3])
        : "r"(a[0]), "r"(a[1]), "r"(a[2]), "r"(a[3]), "r"(b0), "r"(b1));
}

// =================================================================
// LN-fused tensor-core conv1x1 (Cin=64, fp32 in), bf16 3-term split,
// fp16 output. Stages X ONCE, loops out-tiles of 64.
// =================================================================
__global__ void __launch_bounds__(256, 2)
convtc_kernel(const float* __restrict__ in, const float* __restrict__ addp,
              const float* __restrict__ lnw, const float* __restrict__ lnb,
              const float* __restrict__ wt, __half* __restrict__ out,
              int Cout, int shift)
{
    extern __shared__ float sm[];
    float* Xh   = sm;                         // 256 x 272B rows
    uint4* BF   = (uint4*)(sm + 256 * XSTR);  // [4kb][8n8][32] uint4 = 16KB
    float* mu_s = sm + 256 * XSTR + 4096;     // [256]
    float* rs_s = mu_s + 256;                 // [256]
    float* sg_s = rs_s + 256;                 // [64]
    float* sb_s = sg_s + 64;                  // [64]

    int b = blockIdx.z, p0 = blockIdx.x * 256;
    int tid = threadIdx.x, warp = tid >> 5, lane = tid & 31;
    const float* inb = in + (size_t)b * 64 * HW;
    const float* adb = addp ? addp + (size_t)b * 64 * HW : nullptr;

    int p = p0 + tid, ip = p;
    if (shift) {
        int hh = ((p >> 7) + shift) & 127, ww = ((p & 127) + shift) & 127;
        ip = (hh << 7) | ww;
    }
    // ---- stage X once (bf16 hi/lo) + LN stats ----
    float s_sum = 0.f, s_sq = 0.f;
    char* xrow = (char*)Xh + tid * 272;
    #pragma unroll
    for (int j8 = 0; j8 < 8; j8++) {
        uint16_t hb[8], lb[8];
        #pragma unroll
        for (int jj = 0; jj < 8; jj++) {
            int c = j8 * 8 + jj;
            float v = inb[(size_t)c * HW + ip];
            if (adb) v += adb[(size_t)c * HW + ip];
            s_sum += v; s_sq += v * v;
            bsplit(v, hb[jj], lb[jj]);
        }
        *(uint4*)(xrow + j8 * 16) =
            make_uint4(pk2(hb[0], hb[1]), pk2(hb[2], hb[3]), pk2(hb[4], hb[5]), pk2(hb[6], hb[7]));
        *(uint4*)(xrow + 144 + j8 * 16) =
            make_uint4(pk2(lb[0], lb[1]), pk2(lb[2], lb[3]), pk2(lb[4], lb[5]), pk2(lb[6], lb[7]));
    }
    {
        float m = s_sum * 0.015625f;
        float var = s_sq * 0.015625f - m * m;
        mu_s[tid] = m;
        rs_s[tid] = rsqrtf(fmaxf(var, 0.f) + 1e-5f);
    }

    int ntile = (Cout + 63) >> 6;
    for (int t = 0; t < ntile; t++) {
        __syncthreads();
        int o0 = t << 6;
        // ---- stage W fragments (bf16 hi/lo, gamma folded) ----
        #pragma unroll
        for (int i = 0; i < 4; i++) {
            int e = i * 256 + tid;
            int kb = e >> 8, rem = e & 255;
            int n8 = rem >> 5, ln2 = rem & 31;
            int g = ln2 >> 2, t2 = ln2 & 3;
            int og = o0 + n8 * 8 + g;
            int kbase = kb * 16;
            float w0 = 0.f, w1 = 0.f, w2 = 0.f, w3 = 0.f;
            if (og < Cout) {
                const float* wr = wt + (size_t)og * 64 + kbase;
                w0 = wr[2 * t2]     * lnw[kbase + 2 * t2];
                w1 = wr[2 * t2 + 1] * lnw[kbase + 2 * t2 + 1];
                w2 = wr[2 * t2 + 8] * lnw[kbase + 2 * t2 + 8];
                w3 = wr[2 * t2 + 9] * lnw[kbase + 2 * t2 + 9];
            }
            uint16_t h0, l0, h1, l1, h2, l2, h3, l3;
            bsplit(w0, h0, l0); bsplit(w1, h1, l1);
            bsplit(w2, h2, l2); bsplit(w3, h3, l3);
            BF[(kb * 8 + n8) * 32 + ln2] =
                make_uint4(pk2(h0, h1), pk2(h2, h3), pk2(l0, l1), pk2(l2, l3));
        }
        if (tid < 64) {
            float sg = 0.f, sb = 0.f;
            int og = o0 + tid;
            if (og < Cout) {
                const float* wr = wt + (size_t)og * 64;
                #pragma unroll 8
                for (int k = 0; k < 64; k++) { sg += wr[k] * lnw[k]; sb += wr[k] * lnb[k]; }
            }
            sg_s[tid] = sg; sb_s[tid] = sb;
        }
        __syncthreads();

        // ---- tensor GEMM: 4 kb16 steps, 3-term bf16 ----
        float accD[2][8][4] = {};
        uint32_t xbase = (uint32_t)__cvta_generic_to_shared(Xh);
        int r = lane & 7, madd8 = (lane >> 3) & 1, gsel = lane >> 4;
        uint32_t abase = xbase + (warp * 32 + r + madd8 * 8) * 272 + gsel * 16;
        #pragma unroll
        for (int kb = 0; kb < 4; kb++) {
            uint32_t Ah0[4], Ah1[4], Al0[4], Al1[4];
            uint32_t ah = abase + kb * 32;
            ldsm4(Ah0, ah);
            ldsm4(Ah1, ah + 16 * 272);
            ldsm4(Al0, ah + 144);
            ldsm4(Al1, ah + 144 + 16 * 272);
            const uint4* bfk = BF + (size_t)kb * 8 * 32;
            #pragma unroll
            for (int n8 = 0; n8 < 8; n8++) {
                uint4 bv = bfk[n8 * 32 + lane];
                mma_bf16(accD[0][n8], Ah0, bv.x, bv.y);
                mma_bf16(accD[0][n8], Al0, bv.x, bv.y);
                mma_bf16(accD[0][n8], Ah0, bv.z, bv.w);
                mma_bf16(accD[1][n8], Ah1, bv.x, bv.y);
                mma_bf16(accD[1][n8], Al1, bv.x, bv.y);
                mma_bf16(accD[1][n8], Ah1, bv.z, bv.w);
            }
        }
        // ---- epilogue (LN transform, fp16 store) ----
        int gq = lane >> 2, oq = (lane & 3) * 2;
        #pragma unroll
        for (int tt = 0; tt < 2; tt++) {
            int pxa = warp * 32 + tt * 16 + gq;
            int pxb = pxa + 8;
            float mua = mu_s[pxa], rsa_ = rs_s[pxa];
            float mub = mu_s[pxb], rsb = rs_s[pxb];
            #pragma unroll
            for (int n8 = 0; n8 < 8; n8++) {
                #pragma unroll
                for (int q = 0; q < 2; q++) {
                    int ol = n8 * 8 + oq + q;
                    int og = o0 + ol;
                    if (og < Cout) {
                        float sg = sg_s[ol], sb = sb_s[ol];
                        float v0 = rsa_ * (accD[tt][n8][q]     - mua * sg) + sb;
                        float v1 = rsb  * (accD[tt][n8][q + 2] - mub * sg) + sb;
                        size_t obase = ((size_t)b * Cout + og) * HW + p0;
                        out[obase + pxa] = __float2half(v0);
                        out[obase + pxb] = __float2half(v1);
                    }
                }
            }
        }
    }
}

// =================================================================
// gated tensor-core conv (fp16 in, Cin=170 phys 340), bf16 3-term
// =================================================================
__global__ void __launch_bounds__(256, 3)
convgate_kernel(const __half* __restrict__ in, const float* __restrict__ wt,
                float* __restrict__ out, const float* __restrict__ resid)
{
    extern __shared__ float sm[];
    float* Xh = sm;                          // 128 x 272B rows
    uint4* BF = (uint4*)(sm + 128 * XSTR);   // [4kb][8n8][32] uint4

    int b = blockIdx.z, p0 = blockIdx.x * 128;
    int tid = threadIdx.x, warp = tid >> 5, lane = tid & 31;
    int px = tid & 127, half = tid >> 7;
    int ip = p0 + px;
    const __half* inb = in + (size_t)b * 340 * HW;

    float acc[8][4] = {};
    const int kbs16[3] = {4, 4, 3};
    for (int ch = 0; ch < 3; ch++) {
        if (ch) __syncthreads();
        int c0 = ch * 64;
        int nkb = kbs16[ch];
        // ---- stage X: 2 threads/px, 32 channels each ----
        char* xrow = (char*)Xh + px * 272;
        #pragma unroll
        for (int j8 = 0; j8 < 4; j8++) {
            uint16_t hb[8], lb[8];
            #pragma unroll
            for (int jj = 0; jj < 8; jj++) {
                int c = c0 + half * 32 + j8 * 8 + jj;
                float v = 0.f;
                if (c < HIDn) {
                    float a = __half2float(inb[(size_t)c * HW + ip]);
                    float g = __half2float(inb[(size_t)(c + HIDn) * HW + ip]);
                    v = gelu_f(a) * g;
                }
                bsplit(v, hb[jj], lb[jj]);
            }
            *(uint4*)(xrow + half * 64 + j8 * 16) =
                make_uint4(pk2(hb[0], hb[1]), pk2(hb[2], hb[3]), pk2(hb[4], hb[5]), pk2(hb[6], hb[7]));
            *(uint4*)(xrow + 144 + half * 64 + j8 * 16) =
                make_uint4(pk2(lb[0], lb[1]), pk2(lb[2], lb[3]), pk2(lb[4], lb[5]), pk2(lb[6], lb[7]));
        }
        // ---- stage BF ----
        int tot = nkb * 256;
        for (int e = tid; e < tot; e += 256) {
            int kb = e >> 8, rem = e & 255;
            int n8 = rem >> 5, ln2 = rem & 31;
            int g = ln2 >> 2, t2 = ln2 & 3;
            int o = n8 * 8 + g;
            int kbase = c0 + kb * 16;
            int k0 = kbase + 2 * t2, k1 = k0 + 1, k2 = kbase + 2 * t2 + 8, k3 = k2 + 1;
            float w0 = (k0 < HIDn) ? wt[(size_t)o * HIDn + k0] : 0.f;
            float w1 = (k1 < HIDn) ? wt[(size_t)o * HIDn + k1] : 0.f;
            float w2 = (k2 < HIDn) ? wt[(size_t)o * HIDn + k2] : 0.f;
            float w3 = (k3 < HIDn) ? wt[(size_t)o * HIDn + k3] : 0.f;
            uint16_t h0, l0, h1, l1, h2, l2, h3, l3;
            bsplit(w0, h0, l0); bsplit(w1, h1, l1);
            bsplit(w2, h2, l2); bsplit(w3, h3, l3);
            BF[(kb * 8 + n8) * 32 + ln2] =
                make_uint4(pk2(h0, h1), pk2(h2, h3), pk2(l0, l1), pk2(l2, l3));
        }
        __syncthreads();
        // ---- GEMM: warp = 16 px x 64 out ----
        uint32_t xbase = (uint32_t)__cvta_generic_to_shared(Xh);
        int r = lane & 7, madd8 = (lane >> 3) & 1, gsel = lane >> 4;
        uint32_t abase = xbase + (warp * 16 + r + madd8 * 8) * 272 + gsel * 16;
        #pragma unroll
        for (int kb = 0; kb < 4; kb++) {
            if (kb >= nkb) break;
            uint32_t Ah0[4], Al0[4];
            uint32_t ah = abase + kb * 32;
            ldsm4(Ah0, ah);
            ldsm4(Al0, ah + 144);
            const uint4* bfk = BF + (size_t)kb * 8 * 32;
            #pragma unroll
            for (int n8 = 0; n8 < 8; n8++) {
                uint4 bv = bfk[n8 * 32 + lane];
                mma_bf16(acc[n8], Ah0, bv.x, bv.y);
                mma_bf16(acc[n8], Al0, bv.x, bv.y);
                mma_bf16(acc[n8], Ah0, bv.z, bv.w);
            }
        }
    }
    // epilogue: + resid (fp32 out)
    int gq = lane >> 2, oq = (lane & 3) * 2;
    int pxa = warp * 16 + gq, pxb = pxa + 8;
    #pragma unroll
    for (int n8 = 0; n8 < 8; n8++) {
        #pragma unroll
        for (int q = 0; q < 2; q++) {
            int og = n8 * 8 + oq + q;
            size_t obase = ((size_t)b * 64 + og) * HW + p0;
            out[obase + pxa] = acc[n8][q]     + resid[obase + pxa];
            out[obase + pxb] = acc[n8][q + 2] + resid[obase + pxb];
        }
    }
}

// ---------------- depthwise 3x3 conv, fp16 I/O, 8 px/thread ----------------
__global__ void dwconv_kernel(const __half* __restrict__ in, const float* __restrict__ wt,
                              __half* __restrict__ out, int Ch)
{
    int c = blockIdx.y, b = blockIdx.z;
    int p = (blockIdx.x * 256 + threadIdx.x) << 3;
    int h = p >> 7, w0 = p & 127;
    const __half* ib = in + ((size_t)b * Ch + c) * HW;
    const float* wc = wt + c * 9;
    float acc[8] = {0.f,0.f,0.f,0.f,0.f,0.f,0.f,0.f};
    #pragma unroll
    for (int dy = -1; dy <= 1; dy++) {
        int hh = h + dy;
        if ((unsigned)hh > 127u) continue;
        const __half* row = ib + (hh << 7);
        uint4 mraw = *(const uint4*)(row + w0);
        const __half2* m2 = (const __half2*)&mraw;
        float r[10];
        r[0] = (w0 > 0)   ? __half2float(row[w0 - 1]) : 0.f;
        #pragma unroll
        for (int k = 0; k < 4; k++) {
            float2 f = __half22float2(m2[k]);
            r[1 + 2 * k] = f.x; r[2 + 2 * k] = f.y;
        }
        r[9] = (w0 < 120) ? __half2float(row[w0 + 8]) : 0.f;
        float wa = wc[(dy + 1) * 3 + 0], wb = wc[(dy + 1) * 3 + 1], wcc = wc[(dy + 1) * 3 + 2];
        #pragma unroll
        for (int j = 0; j < 8; j++)
            acc[j] += wa * r[j] + wb * r[j + 1] + wcc * r[j + 2];
    }
    __half2 o2[4];
    #pragma unroll
    for (int k = 0; k < 4; k++) o2[k] = __floats2half2_rn(acc[2 * k], acc[2 * k + 1]);
    *(uint4*)(out + ((size_t)b * Ch + c) * HW + p) = *(uint4*)o2;
}

// =================================================================
// RSA window attention (fp16 qkv in) + fused proj conv + inverse roll
// =================================================================
__global__ void __launch_bounds__(256, 3)
rsa_attn_kernel(const __half* __restrict__ qkv, const float* __restrict__ pw,
                float* __restrict__ out, const float* __restrict__ temp)
{
    extern __shared__ float sm[];
    float* A   = sm;
    float* B   = sm + 64 * WSTR;
    float* C   = sm + 2 * 64 * WSTR;
    float* Pw  = sm + 3 * 64 * WSTR;
    float* inv = Pw + 64 * WSTR;
    int blk = blockIdx.x;
    int b = blk >> 8, win = blk & 255;
    int wy = win >> 4, wx = win & 15;
    int tid = threadIdx.x;
    size_t qbase = (size_t)b * 192 * HW;

    for (int e = tid; e < 4096; e += 256) {
        int p = e & 63, c = e >> 6;
        int gp = (((wy << 3) + (p >> 3)) << 7) | ((wx << 3) + (p & 7));
        A[p * WSTR + c] = __half2float(qkv[qbase + c * HW + gp]);
        B[p * WSTR + c] = __half2float(qkv[qbase + (64 + c) * HW + gp]);
        Pw[(e & 63) * WSTR + (e >> 6)] = pw[e];
    }
    __syncthreads();
    if (tid < 64) {
        int p = tid;
        float nq = 0.f, nk = 0.f;
        #pragma unroll
        for (int c = 0; c < 64; c++) {
            float a = A[p * WSTR + c]; nq += a * a;
            float bb = B[p * WSTR + c]; nk += bb * bb;
        }
        inv[p] = 1.0f / (fmaxf(sqrtf(nq), 1e-12f) * fmaxf(sqrtf(nk), 1e-12f));
    }
    __syncthreads();
    for (int e4 = tid; e4 < 1024; e4 += 256) {
        int p = e4 >> 4, c4 = e4 & 15;
        float iv = inv[p];
        float4 v = ((float4*)B)[p * (WSTR / 4) + c4];
        v.x *= iv; v.y *= iv; v.z *= iv; v.w *= iv;
        ((float4*)B)[p * (WSTR / 4) + c4] = v;
    }
    __syncthreads();
    float tscale = temp[0];
    {   // GEMM1: attn
        int c0 = (tid >> 4) << 2, d0 = (tid & 15) << 2;
        float s[4][4] = {};
        #pragma unroll 4
        for (int p = 0; p < 64; p++) {
            float4 qv = *(const float4*)(A + p * WSTR + c0);
            float4 kv = *(const float4*)(B + p * WSTR + d0);
            float qr[4] = {qv.x, qv.y, qv.z, qv.w};
            float kr[4] = {kv.x, kv.y, kv.z, kv.w};
            #pragma unroll
            for (int i = 0; i < 4; i++)
                #pragma unroll
                for (int j = 0; j < 4; j++) s[i][j] += qr[i] * kr[j];
        }
        #pragma unroll
        for (int i = 0; i < 4; i++)
            *(float4*)(C + (c0 + i) * WSTR + d0) =
                make_float4(fmaxf(0.f, tscale * s[i][0]), fmaxf(0.f, tscale * s[i][1]),
                            fmaxf(0.f, tscale * s[i][2]), fmaxf(0.f, tscale * s[i][3]));
    }
    __syncthreads();
    for (int e = tid; e < 4096; e += 256) {
        int p = e & 63, c = e >> 6;
        int gp = (((wy << 3) + (p >> 3)) << 7) | ((wx << 3) + (p & 7));
        A[c * WSTR + p] = __half2float(qkv[qbase + (128 + c) * HW + gp]);
    }
    __syncthreads();
    {   // GEMM2: out[d][p]
        int p0 = (tid >> 4) << 2, d0 = (tid & 15) << 2;
        float s[4][4] = {};
        #pragma unroll 4
        for (int c = 0; c < 64; c++) {
            float4 vv = *(const float4*)(A + c * WSTR + p0);
            float4 av = *(const float4*)(C + c * WSTR + d0);
            float vr[4] = {vv.x, vv.y, vv.z, vv.w};
            float ar[4] = {av.x, av.y, av.z, av.w};
            #pragma unroll
            for (int i = 0; i < 4; i++)
                #pragma unroll
                for (int j = 0; j < 4; j++) s[i][j] += vr[i] * ar[j];
        }
        #pragma unroll
        for (int j = 0; j < 4; j++)
            *(float4*)(B + (d0 + j) * WSTR + p0) = make_float4(s[0][j], s[1][j], s[2][j], s[3][j]);
    }
    __syncthreads();
    {   // GEMM3: proj
        int o0 = (tid >> 4) << 2, p0 = (tid & 15) << 2;
        float s[4][4] = {};
        #pragma unroll 4
        for (int d = 0; d < 64; d++) {
            float4 wv = *(const float4*)(Pw + d * WSTR + o0);
            float4 bv = *(const float4*)(B + d * WSTR + p0);
            float wr[4] = {wv.x, wv.y, wv.z, wv.w};
            float br[4] = {bv.x, bv.y, bv.z, bv.w};
            #pragma unroll
            for (int i = 0; i < 4; i++)
                #pragma unroll
                for (int j = 0; j < 4; j++) s[i][j] += wr[i] * br[j];
        }
        #pragma unroll
        for (int i = 0; i < 4; i++)
            *(float4*)(C + (o0 + i) * WSTR + p0) = make_float4(s[i][0], s[i][1], s[i][2], s[i][3]);
    }
    __syncthreads();
    size_t obase = (size_t)b * 64 * HW;
    for (int e = tid; e < 4096; e += 256) {
        int p = e & 63, o = e >> 6;
        int gh = (((wy << 3) + (p >> 3)) + 4) & 127;
        int gw = (((wx << 3) + (p & 7)) + 4) & 127;
        out[obase + o * HW + (gh << 7) + gw] = C[o * WSTR + p];
    }
}

// ---------------- GSA: partial Gram sums (fp16 qkv in) ---------------------------
__global__ void gsa_attn_part(const __half* __restrict__ qkv, float* __restrict__ part)
{
    __shared__ float red[8][80];
    int bh = blockIdx.y;
    int b = bh >> 3, hd = bh & 7;
    int chunk = blockIdx.x;
    int tid = threadIdx.x;
    const __half* qb = qkv + ((size_t)b * 192 + hd * 8) * HW;
    const __half* kb = qkv + ((size_t)b * 192 + 64 + hd * 8) * HW;
    float dot[8][8] = {};
    float qn[8] = {}, kn[8] = {};
    int n0 = chunk * 2048;
    for (int n = n0 + tid; n < n0 + 2048; n += 256) {
        float qv[8], kv[8];
        #pragma unroll
        for (int i = 0; i < 8; i++) {
            qv[i] = __half2float(qb[i * HW + n]);
            kv[i] = __half2float(kb[i * HW + n]);
        }
        #pragma unroll
        for (int i = 0; i < 8; i++) { qn[i] += qv[i] * qv[i]; kn[i] += kv[i] * kv[i]; }
        #pragma unroll
        for (int i = 0; i < 8; i++)
            #pragma unroll
            for (int j = 0; j < 8; j++) dot[i][j] += qv[i] * kv[j];
    }
    int lane = tid & 31, w = tid >> 5;
    #pragma unroll
    for (int i = 0; i < 8; i++)
        #pragma unroll
        for (int j = 0; j < 8; j++) {
            float v = dot[i][j];
            #pragma unroll
            for (int off = 16; off; off >>= 1) v += __shfl_xor_sync(0xffffffffu, v, off);
            if (lane == 0) red[w][i * 8 + j] = v;
        }
    #pragma unroll
    for (int i = 0; i < 8; i++) {
        float v = qn[i];
        #pragma unroll
        for (int off = 16; off; off >>= 1) v += __shfl_xor_sync(0xffffffffu, v, off);
        if (lane == 0) red[w][64 + i] = v;
        float u = kn[i];
        #pragma unroll
        for (int off = 16; off; off >>= 1) u += __shfl_xor_sync(0xffffffffu, u, off);
        if (lane == 0) red[w][72 + i] = u;
    }
    __syncthreads();
    if (tid < 80) {
        float s = 0.f;
        #pragma unroll
        for (int w2 = 0; w2 < 8; w2++) s += red[w2][tid];
        part[((size_t)bh * 8 + chunk) * 80 + tid] = s;
    }
}

__global__ void gsa_attn_final(const float* __restrict__ part, float* __restrict__ attn,
                               const float* __restrict__ temp)
{
    __shared__ float fin[80];
    int bh = blockIdx.x, tid = threadIdx.x;
    if (tid < 80) {
        float s = 0.f;
        #pragma unroll
        for (int c = 0; c < 8; c++) s += part[((size_t)bh * 8 + c) * 80 + tid];
        fin[tid] = s;
    }
    __syncthreads();
    if (tid < 64) {
        int c = tid >> 3, d = tid & 7;
        float nq = fmaxf(sqrtf(fin[64 + c]), 1e-12f);
        float nk = fmaxf(sqrtf(fin[72 + d]), 1e-12f);
        attn[(size_t)bh * 64 + tid] = fmaxf(0.f, temp[0] * fin[tid] / (nq * nk));
    }
}

// ---------------- GSA: fold proj into attention matrix -------------------------
__global__ void gsa_makeM(const float* __restrict__ attn, const float* __restrict__ pw,
                          float* __restrict__ M)
{
    __shared__ float at[512];
    int b = blockIdx.x, tid = threadIdx.x;
    for (int e = tid; e < 512; e += 256) at[e] = attn[(size_t)b * 512 + e];
    __syncthreads();
    for (int t = 0; t < 16; t++) {
        int e = t * 256 + tid;
        int o = e >> 6, chp = e & 63;
        int hd = chp >> 3, d = chp & 7;
        float s = 0.f;
        #pragma unroll
        for (int c = 0; c < 8; c++)
            s += pw[(size_t)o * 64 + c * 8 + hd] * at[hd * 64 + c * 8 + d];
        M[(size_t)b * 4096 + e] = s;
    }
}

// ---------------- GSA: out = M @ v (fp16 v in, proj included) --------------------
__global__ void gsa_mv_kernel(const __half* __restrict__ qkv, const float* __restrict__ M,
                              float* __restrict__ out)
{
    __shared__ float Ms[4096];
    int b = blockIdx.y, tid = threadIdx.x;
    for (int e = tid; e < 4096; e += 256) Ms[e] = M[(size_t)b * 4096 + e];
    __syncthreads();
    int n = blockIdx.x * 256 + tid;
    const __half* vb = qkv + ((size_t)b * 192 + 128) * HW + n;
    float* ob = out + (size_t)b * 64 * HW + n;
    float vv[64];
    #pragma unroll
    for (int c = 0; c < 64; c++) vv[c] = __half2float(vb[(size_t)c * HW]);
    #pragma unroll
    for (int og = 0; og < 8; og++) {
        float acc[8] = {0.f,0.f,0.f,0.f,0.f,0.f,0.f,0.f};
        #pragma unroll
        for (int c = 0; c < 64; c++) {
            float v = vv[c];
            #pragma unroll
            for (int j = 0; j < 8; j++) acc[j] += Ms[(og * 8 + j) * 64 + c] * v;
        }
        #pragma unroll
        for (int j = 0; j < 8; j++) ob[(size_t)(og * 8 + j) * HW] = acc[j];
    }
}

// ---------------- launch ---------------------------------------------------------
extern "C" void kernel_launch(void* const* d_in, const int* in_sizes, int n_in,
                              void* d_out, int out_size)
{
    const float* x         = (const float*)d_in[0];
    const float* ln_s0_w   = (const float*)d_in[1];
    const float* ln_s0_b   = (const float*)d_in[2];
    const float* ln_s2_w   = (const float*)d_in[3];
    const float* ln_s2_b   = (const float*)d_in[4];
    const float* rsa_qkv_w = (const float*)d_in[5];
    const float* rsa_dw_w  = (const float*)d_in[6];
    const float* rsa_proj_w= (const float*)d_in[7];
    const float* rsa_temp  = (const float*)d_in[8];
    const float* ffs_in_w  = (const float*)d_in[9];
    const float* ffs_dw_w  = (const float*)d_in[10];
    const float* ffs_out_w = (const float*)d_in[11];
    const float* ln_c0_w   = (const float*)d_in[12];
    const float* ln_c0_b   = (const float*)d_in[13];
    const float* ln_c2_w   = (const float*)d_in[14];
    const float* ln_c2_b   = (const float*)d_in[15];
    const float* gsa_qkv_w = (const float*)d_in[16];
    const float* gsa_dw_w  = (const float*)d_in[17];
    const float* gsa_proj_w= (const float*)d_in[18];
    const float* gsa_temp  = (const float*)d_in[19];
    const float* ffc_in_w  = (const float*)d_in[20];
    const float* ffc_dw_w  = (const float*)d_in[21];
    const float* ffc_out_w = (const float*)d_in[22];
    float* outp = (float*)d_out;

    float *bufR, *bufX, *bufG, *attnb, *partb, *Mb;
    __half *big1, *big2;
    cudaGetSymbolAddress((void**)&bufR,  g_bufR);
    cudaGetSymbolAddress((void**)&bufX,  g_bufX);
    cudaGetSymbolAddress((void**)&bufG,  g_bufG);
    cudaGetSymbolAddress((void**)&big1,  g_big1);
    cudaGetSymbolAddress((void**)&big2,  g_big2);
    cudaGetSymbolAddress((void**)&attnb, g_attn);
    cudaGetSymbolAddress((void**)&partb, g_part);
    cudaGetSymbolAddress((void**)&Mb,    g_M);

    const int ctc_smem = (256 * XSTR + 4096 + 256 + 256 + 64 + 64) * (int)sizeof(float); // 88576
    const int cg_smem  = (128 * XSTR + 4096) * (int)sizeof(float);                       // 51200
    const int rsa_smem = (4 * 64 * WSTR + 64) * (int)sizeof(float);
    cudaFuncSetAttribute(convtc_kernel, cudaFuncAttributeMaxDynamicSharedMemorySize, ctc_smem);
    cudaFuncSetAttribute(convgate_kernel, cudaFuncAttributeMaxDynamicSharedMemorySize, cg_smem);
    cudaFuncSetAttribute(rsa_attn_kernel, cudaFuncAttributeMaxDynamicSharedMemorySize, rsa_smem);

    // ---- stage 1: RSA + spatial FFN ----
    convtc_kernel<<<dim3(64, 1, Bn), 256, ctc_smem>>>(x, nullptr, ln_s0_w, ln_s0_b, rsa_qkv_w, big1, 192, 4);
    dwconv_kernel<<<dim3(8, 192, Bn), 256>>>(big1, rsa_dw_w, big2, 192);
    rsa_attn_kernel<<<Bn * 256, 256, rsa_smem>>>(big2, rsa_proj_w, bufR, rsa_temp);
    convtc_kernel<<<dim3(64, 1, Bn), 256, ctc_smem>>>(bufR, x, ln_s2_w, ln_s2_b, ffs_in_w, big1, 340, 0);
    dwconv_kernel<<<dim3(8, 340, Bn), 256>>>(big1, ffs_dw_w, big2, 340);
    convgate_kernel<<<dim3(128, 1, Bn), 256, cg_smem>>>(big2, ffs_out_w, bufX, bufR);

    // ---- stage 2: GSA + channel FFN ----
    convtc_kernel<<<dim3(64, 1, Bn), 256, ctc_smem>>>(bufX, nullptr, ln_c0_w, ln_c0_b, gsa_qkv_w, big1, 192, 0);
    dwconv_kernel<<<dim3(8, 192, Bn), 256>>>(big1, gsa_dw_w, big2, 192);
    gsa_attn_part<<<dim3(8, 64), 256>>>(big2, partb);
    gsa_attn_final<<<64, 128>>>(partb, attnb, gsa_temp);
    gsa_makeM<<<Bn, 256>>>(attnb, gsa_proj_w, Mb);
    gsa_mv_kernel<<<dim3(64, Bn), 256>>>(big2, Mb, bufG);
    convtc_kernel<<<dim3(64, 1, Bn), 256, ctc_smem>>>(bufG, bufX, ln_c2_w, ln_c2_b, ffc_in_w, big1, 340, 0);
    dwconv_kernel<<<dim3(8, 340, Bn), 256>>>(big1, ffc_dw_w, big2, 340);
    convgate_kernel<<<dim3(128, 1, Bn), 256, cg_smem>>>(big2, ffc_out_w, outp, bufG);
}